// round 11
// baseline (speedup 1.0000x reference)
#include <cuda_runtime.h>

// Problem constants
#define BB   32
#define TT   256
#define ESZ  128
#define HH   64
#define H4   256
#define H2   128
#define UU   64
#define NEE  256
#define NROW (BB*TT)   // 8192

// Scratch (device globals: no allocations allowed)
__device__ float g_xw [4][NROW][H4];        // input projections + bias, per (net,dir)
__device__ float g_rnn[2][BB][TT][H2];      // bilstm outputs (concat fwd/bwd)
__device__ float g_ent[2][BB][NEE][H2];     // 0: wordent, 1: dataent
__device__ float g_enc[BB][NEE][UU];        // dataent @ W1^T
__device__ float g_dec[BB][NEE][UU];        // wordent @ W2^T

__device__ __forceinline__ float tanha(float x) {
    float y; asm("tanh.approx.f32 %0, %1;" : "=f"(y) : "f"(x)); return y;
}
__device__ __forceinline__ float siga(float x) {   // sigmoid via MUFU.TANH
    return 0.5f + 0.5f * tanha(0.5f * x);
}
__device__ __forceinline__ unsigned f2tf32(float x) {
    unsigned r; asm("cvt.rna.tf32.f32 %0, %1;" : "=r"(r) : "f"(x)); return r;
}
__device__ __forceinline__ void mma_tf32(
    float& c0, float& c1, float& c2, float& c3,
    unsigned a0, unsigned a1, unsigned a2, unsigned a3,
    unsigned b0, unsigned b1)
{
    asm volatile(
        "mma.sync.aligned.m16n8k8.row.col.f32.tf32.tf32.f32 "
        "{%0,%1,%2,%3}, {%4,%5,%6,%7}, {%8,%9}, {%0,%1,%2,%3};"
        : "+f"(c0), "+f"(c1), "+f"(c2), "+f"(c3)
        : "r"(a0), "r"(a1), "r"(a2), "r"(a3), "r"(b0), "r"(b1));
}

// Shared tile layout: rows padded to 36 floats (36*4=144B = 9*16B: float4-aligned,
// and frag loads (4g+q addressing) are bank-conflict-free).
#define KPAD 36

// ---------------------------------------------------------------------------
// K1: fused embedding gather + input GEMM via tf32 tensor cores (round-6 cfg):
//   g_xw[combo][row][col] = b[col] + emb[tok[row]] . Wi[col]
// Block tile 128 rows x 64 cols, K=128 in 32-chunks. 8 warps, each 32x32.
// grid: (NROW/128, 4, 4): x=rowblk, y=colblk, z=combo.
// ---------------------------------------------------------------------------
__global__ __launch_bounds__(256) void k_xw(
    const int* __restrict__ sents, const int* __restrict__ datas,
    const float* __restrict__ emb,
    const float* __restrict__ Wi0, const float* __restrict__ b0,
    const float* __restrict__ Wi1, const float* __restrict__ b1,
    const float* __restrict__ Wi2, const float* __restrict__ b2,
    const float* __restrict__ Wi3, const float* __restrict__ b3)
{
    const int combo = blockIdx.z;
    const float* Wi = (combo == 0) ? Wi0 : (combo == 1) ? Wi1 : (combo == 2) ? Wi2 : Wi3;
    const float* bv = (combo == 0) ? b0  : (combo == 1) ? b1  : (combo == 2) ? b2  : b3;
    const int* toks = (combo < 2) ? sents : datas;

    __shared__ float As[128][KPAD];
    __shared__ float Bs[64][KPAD];
    __shared__ int   stok[128];

    const int tid = threadIdx.x;
    const int rowbase = blockIdx.x * 128;
    const int colbase = blockIdx.y * 64;

    if (tid < 128) stok[tid] = toks[rowbase + tid];

    const int warp = tid >> 5;
    const int lane = tid & 31;
    const int wr = (warp >> 1) * 32;       // warp row offset within tile
    const int wc = (warp & 1) * 32;        // warp col offset within tile
    const int rg = lane >> 2;              // 0..7
    const int q  = lane & 3;               // 0..3

    float c[2][4][4];                       // [mtile][ntile][frag]
    #pragma unroll
    for (int mt = 0; mt < 2; mt++)
        #pragma unroll
        for (int nt = 0; nt < 4; nt++)
            #pragma unroll
            for (int i = 0; i < 4; i++) c[mt][nt][i] = 0.0f;

    __syncthreads();

    for (int ks = 0; ks < 128; ks += 32) {
        // Load A: 128 rows x 32 k = 1024 float4 / 256 thr = 4 each (gathered emb)
        #pragma unroll
        for (int i = 0; i < 4; i++) {
            int lin = i * 256 + tid;
            int r  = lin >> 3;            // 0..127
            int kq = lin & 7;             // 0..7
            float4 av = *(const float4*)&emb[(size_t)stok[r] * ESZ + ks + kq * 4];
            *(float4*)&As[r][kq * 4] = av;
        }
        // Load B: 64 cols x 32 k = 512 float4 / 256 thr = 2 each
        #pragma unroll
        for (int i = 0; i < 2; i++) {
            int lin = i * 256 + tid;
            int r  = lin >> 3;            // 0..63
            int kq = lin & 7;
            float4 wv = *(const float4*)&Wi[(size_t)(colbase + r) * ESZ + ks + kq * 4];
            *(float4*)&Bs[r][kq * 4] = wv;
        }
        __syncthreads();

        #pragma unroll
        for (int kk = 0; kk < 32; kk += 8) {
            unsigned a[2][4], b[4][2];
            #pragma unroll
            for (int mt = 0; mt < 2; mt++) {
                int r = wr + 16 * mt + rg;
                a[mt][0] = f2tf32(As[r    ][kk + q]);
                a[mt][1] = f2tf32(As[r + 8][kk + q]);
                a[mt][2] = f2tf32(As[r    ][kk + q + 4]);
                a[mt][3] = f2tf32(As[r + 8][kk + q + 4]);
            }
            #pragma unroll
            for (int nt = 0; nt < 4; nt++) {
                int n = wc + 8 * nt + rg;
                b[nt][0] = f2tf32(Bs[n][kk + q]);
                b[nt][1] = f2tf32(Bs[n][kk + q + 4]);
            }
            #pragma unroll
            for (int mt = 0; mt < 2; mt++)
                #pragma unroll
                for (int nt = 0; nt < 4; nt++)
                    mma_tf32(c[mt][nt][0], c[mt][nt][1], c[mt][nt][2], c[mt][nt][3],
                             a[mt][0], a[mt][1], a[mt][2], a[mt][3],
                             b[nt][0], b[nt][1]);
        }
        __syncthreads();
    }

    // Epilogue: add bias, write g_xw
    #pragma unroll
    for (int mt = 0; mt < 2; mt++) {
        int r = rowbase + wr + 16 * mt + rg;
        #pragma unroll
        for (int nt = 0; nt < 4; nt++) {
            int col = colbase + wc + 8 * nt + 2 * q;
            float bx = bv[col], by = bv[col + 1];
            float2 v0 = make_float2(c[mt][nt][0] + bx, c[mt][nt][1] + by);
            float2 v1 = make_float2(c[mt][nt][2] + bx, c[mt][nt][3] + by);
            *(float2*)&g_xw[combo][r    ][col] = v0;
            *(float2*)&g_xw[combo][r + 8][col] = v1;
        }
    }
}

// ---------------------------------------------------------------------------
// K2: LSTM recurrence, split-K over paired threads (512 threads/block).
// Thread tid: row r = tid>>1, k-half = tid&1 (32 Wh coeffs in registers).
// Per step: 8 LDS.128 + 32 FMA (4 chains of 8) + shfl_xor(1) half-combine.
// 16 warps/SM (vs 8) with half-depth chains -> higher IPC on the same
// instruction volume. Gate phase identical to the round-6 version.
// ---------------------------------------------------------------------------
__global__ __launch_bounds__(512) void k_lstm(
    const float* __restrict__ Wh0, const float* __restrict__ Wh1,
    const float* __restrict__ Wh2, const float* __restrict__ Wh3)
{
    const int b = blockIdx.x;
    const int combo = blockIdx.y;
    const int net = combo >> 1;
    const int dir = combo & 1;
    const float* Wh = (combo == 0) ? Wh0 : (combo == 1) ? Wh1 : (combo == 2) ? Wh2 : Wh3;

    const int tid  = threadIdx.x;
    const int r    = tid >> 1;     // z row 0..255
    const int half = tid & 1;      // k-half: [0,32) or [32,64)

    // 32 Wh coefficients for (row r, this k-half)
    float wh[32];
    const float* wrow = Wh + (size_t)r * HH + half * 32;
    #pragma unroll
    for (int k4 = 0; k4 < 8; k4++) {
        float4 t4 = *(const float4*)&wrow[k4 * 4];
        wh[k4*4+0] = t4.x; wh[k4*4+1] = t4.y; wh[k4*4+2] = t4.z; wh[k4*4+3] = t4.w;
    }

    __shared__ __align__(16) float h_s[HH];
    __shared__ float z_s[H4];
    float cst = 0.0f;
    if (tid < HH) h_s[tid] = 0.0f;

    const float* xwp = &g_xw[combo][b * TT][0];
    const int tstep = dir ? -1 : 1;
    int t = dir ? (TT - 1) : 0;
    float xcur = xwp[t * H4 + r];          // both halves load (broadcast), half0 uses
    __syncthreads();

    for (int ti = 0; ti < TT; ti++) {
        // prefetch next step's input projection (off critical path)
        float xnext = (ti + 1 < TT) ? xwp[(t + tstep) * H4 + r] : 0.0f;

        const float4* hv4 = ((const float4*)h_s) + half * 8;
        float a0 = half ? 0.0f : xcur, a1 = 0.0f, a2 = 0.0f, a3 = 0.0f;
        #pragma unroll
        for (int k4 = 0; k4 < 8; k4 += 4) {
            float4 h0 = hv4[k4 + 0];
            float4 h1 = hv4[k4 + 1];
            float4 h2 = hv4[k4 + 2];
            float4 h3 = hv4[k4 + 3];
            a0 = fmaf(wh[(k4+0)*4+0], h0.x, a0);
            a0 = fmaf(wh[(k4+0)*4+1], h0.y, a0);
            a0 = fmaf(wh[(k4+0)*4+2], h0.z, a0);
            a0 = fmaf(wh[(k4+0)*4+3], h0.w, a0);
            a1 = fmaf(wh[(k4+1)*4+0], h1.x, a1);
            a1 = fmaf(wh[(k4+1)*4+1], h1.y, a1);
            a1 = fmaf(wh[(k4+1)*4+2], h1.z, a1);
            a1 = fmaf(wh[(k4+1)*4+3], h1.w, a1);
            a2 = fmaf(wh[(k4+2)*4+0], h2.x, a2);
            a2 = fmaf(wh[(k4+2)*4+1], h2.y, a2);
            a2 = fmaf(wh[(k4+2)*4+2], h2.z, a2);
            a2 = fmaf(wh[(k4+2)*4+3], h2.w, a2);
            a3 = fmaf(wh[(k4+3)*4+0], h3.x, a3);
            a3 = fmaf(wh[(k4+3)*4+1], h3.y, a3);
            a3 = fmaf(wh[(k4+3)*4+2], h3.z, a3);
            a3 = fmaf(wh[(k4+3)*4+3], h3.w, a3);
        }
        const float part = (a0 + a1) + (a2 + a3);
        const float z = part + __shfl_xor_sync(0xFFFFFFFFu, part, 1);

        if (!half) z_s[r] = z;
        __syncthreads();

        if (tid < HH) {
            float iv = siga(z_s[tid]);
            float fv = siga(z_s[tid + HH]);
            float gv = tanha(z_s[tid + 2*HH]);
            float ov = siga(z_s[tid + 3*HH]);
            cst = fv * cst + iv * gv;
            float hv = ov * tanha(cst);
            h_s[tid] = hv;
            g_rnn[net][b][t][dir * HH + tid] = hv;
        }
        __syncthreads();
        xcur = xnext;
        t += tstep;
    }
}

// ---------------------------------------------------------------------------
// K3: entity extraction (segment means). One block per (b, which).
// ---------------------------------------------------------------------------
__global__ __launch_bounds__(128) void k_ent(
    const int* __restrict__ slab, const int* __restrict__ dlab)
{
    const int b = blockIdx.x;
    const int which = blockIdx.y;
    const int* lab = which ? dlab : slab;

    __shared__ int s_eid[TT];
    __shared__ int s_cnt[TT];
    __shared__ int s_closed;

    const int f = threadIdx.x;
    s_cnt[f] = 0; s_cnt[f + 128] = 0;
    __syncthreads();

    if (f == 0) {
        bool st = false; int ne = 0;
        for (int t = 0; t < TT; t++) {
            int l = lab[b * TT + t];
            if (l == 1)      { st = true; ne++; }
            else if (l == 0) { st = false; }
            if (st) { s_eid[t] = ne - 1; s_cnt[ne - 1]++; }
            else    { s_eid[t] = -1; }
        }
        s_closed = ne - (st ? 1 : 0);
    }
    __syncthreads();

    const int closed = s_closed;
    float* dst = &g_ent[which][b][0][0];
    for (int e = 0; e < NEE; e++) dst[e * H2 + f] = 0.0f;

    const float* src = &g_rnn[which][b][0][0];
    float acc = 0.0f; int cur = -1;
    for (int t = 0; t < TT; t++) {
        int e = s_eid[t];
        if (e != cur) {
            if (cur >= 0 && cur < closed) dst[cur * H2 + f] = acc / (float)s_cnt[cur];
            acc = 0.0f; cur = e;
        }
        if (e >= 0) acc += src[t * H2 + f];
    }
    if (cur >= 0 && cur < closed) dst[cur * H2 + f] = acc / (float)s_cnt[cur];
}

// ---------------------------------------------------------------------------
// K4: enc/dec projections via tf32 tensor cores.
// z=0: g_enc = dataent @ W1^T; z=1: g_dec = wordent @ W2^T
// Block tile 128 rows x 64 cols (full N), K=128 in 32-chunks. grid (64, 2).
// ---------------------------------------------------------------------------
__global__ __launch_bounds__(256) void k_encdec(
    const float* __restrict__ W1, const float* __restrict__ W2)
{
    const int z = blockIdx.y;
    const float* src = (z == 0) ? &g_ent[1][0][0][0] : &g_ent[0][0][0][0];
    const float* W   = (z == 0) ? W1 : W2;
    float* dst       = (z == 0) ? &g_enc[0][0][0] : &g_dec[0][0][0];

    __shared__ float As[128][KPAD];
    __shared__ float Bs[64][KPAD];

    const int tid = threadIdx.x;
    const int rowbase = blockIdx.x * 128;

    const int warp = tid >> 5;
    const int lane = tid & 31;
    const int wr = (warp >> 1) * 32;
    const int wc = (warp & 1) * 32;
    const int rg = lane >> 2;
    const int q  = lane & 3;

    float c[2][4][4];
    #pragma unroll
    for (int mt = 0; mt < 2; mt++)
        #pragma unroll
        for (int nt = 0; nt < 4; nt++)
            #pragma unroll
            for (int i = 0; i < 4; i++) c[mt][nt][i] = 0.0f;

    for (int ks = 0; ks < 128; ks += 32) {
        #pragma unroll
        for (int i = 0; i < 4; i++) {
            int lin = i * 256 + tid;
            int r  = lin >> 3;
            int kq = lin & 7;
            float4 av = *(const float4*)&src[(size_t)(rowbase + r) * H2 + ks + kq * 4];
            *(float4*)&As[r][kq * 4] = av;
        }
        #pragma unroll
        for (int i = 0; i < 2; i++) {
            int lin = i * 256 + tid;
            int r  = lin >> 3;
            int kq = lin & 7;
            float4 wv = *(const float4*)&W[(size_t)r * H2 + ks + kq * 4];
            *(float4*)&Bs[r][kq * 4] = wv;
        }
        __syncthreads();

        #pragma unroll
        for (int kk = 0; kk < 32; kk += 8) {
            unsigned a[2][4], b[4][2];
            #pragma unroll
            for (int mt = 0; mt < 2; mt++) {
                int r = wr + 16 * mt + rg;
                a[mt][0] = f2tf32(As[r    ][kk + q]);
                a[mt][1] = f2tf32(As[r + 8][kk + q]);
                a[mt][2] = f2tf32(As[r    ][kk + q + 4]);
                a[mt][3] = f2tf32(As[r + 8][kk + q + 4]);
            }
            #pragma unroll
            for (int nt = 0; nt < 4; nt++) {
                int n = wc + 8 * nt + rg;
                b[nt][0] = f2tf32(Bs[n][kk + q]);
                b[nt][1] = f2tf32(Bs[n][kk + q + 4]);
            }
            #pragma unroll
            for (int mt = 0; mt < 2; mt++)
                #pragma unroll
                for (int nt = 0; nt < 4; nt++)
                    mma_tf32(c[mt][nt][0], c[mt][nt][1], c[mt][nt][2], c[mt][nt][3],
                             a[mt][0], a[mt][1], a[mt][2], a[mt][3],
                             b[nt][0], b[nt][1]);
        }
        __syncthreads();
    }

    #pragma unroll
    for (int mt = 0; mt < 2; mt++) {
        int r = rowbase + wr + 16 * mt + rg;
        #pragma unroll
        for (int nt = 0; nt < 4; nt++) {
            int col = wc + 8 * nt + 2 * q;
            *(float2*)&dst[(size_t)r * UU + col] =
                make_float2(c[mt][nt][0], c[mt][nt][1]);
            *(float2*)&dst[(size_t)(r + 8) * UU + col] =
                make_float2(c[mt][nt][2], c[mt][nt][3]);
        }
    }
}

// ---------------------------------------------------------------------------
// K5: logits[b][w][d] = sum_u v[u] * tanh(enc[b][d][u] + dec[b][w][u])
// Block: (b, 32-w tile, 64-d tile). Hardware tanh.approx (MUFU.TANH).
// ---------------------------------------------------------------------------
__global__ __launch_bounds__(256) void k_logits(
    const float* __restrict__ v, float* __restrict__ out)
{
    const int b = blockIdx.x, wt = blockIdx.y, dt = blockIdx.z;

    __shared__ float enc_s[64][68];
    __shared__ float dec_s[32][68];
    __shared__ __align__(16) float v_s[64];

    const int tid = threadIdx.x;
    if (tid < 64) v_s[tid] = v[tid];

    #pragma unroll
    for (int i = 0; i < 4; i++) {
        int lin = i * 256 + tid;
        int d = lin >> 4, u4 = lin & 15;
        float4 val = *(const float4*)&g_enc[b][dt * 64 + d][u4 * 4];
        *(float4*)&enc_s[d][u4 * 4] = val;
    }
    #pragma unroll
    for (int i = 0; i < 2; i++) {
        int lin = i * 256 + tid;
        int w = lin >> 4, u4 = lin & 15;
        float4 val = *(const float4*)&g_dec[b][wt * 32 + w][u4 * 4];
        *(float4*)&dec_s[w][u4 * 4] = val;
    }
    __syncthreads();

    const int wloc = tid >> 3;     // 0..31
    const int dg   = tid & 7;      // 0..7
    float acc[8] = {0.f, 0.f, 0.f, 0.f, 0.f, 0.f, 0.f, 0.f};

    #pragma unroll
    for (int u4 = 0; u4 < 16; u4++) {
        float4 dv = *(const float4*)&dec_s[wloc][u4 * 4];
        float4 vv = *(const float4*)&v_s[u4 * 4];
        #pragma unroll
        for (int jj = 0; jj < 8; jj++) {
            float4 ev = *(const float4*)&enc_s[dg + 8 * jj][u4 * 4];
            acc[jj] = fmaf(vv.x, tanha(ev.x + dv.x), acc[jj]);
            acc[jj] = fmaf(vv.y, tanha(ev.y + dv.y), acc[jj]);
            acc[jj] = fmaf(vv.z, tanha(ev.z + dv.z), acc[jj]);
            acc[jj] = fmaf(vv.w, tanha(ev.w + dv.w), acc[jj]);
        }
    }

    const int w = wt * 32 + wloc;
    float* op = out + ((size_t)b * NEE + w) * NEE + dt * 64;
    #pragma unroll
    for (int jj = 0; jj < 8; jj++) op[dg + 8 * jj] = acc[jj];
}

// ---------------------------------------------------------------------------
// K6: in-place row softmax over last dim (256). One warp per row.
// ---------------------------------------------------------------------------
__global__ __launch_bounds__(256) void k_softmax(float* __restrict__ out)
{
    const int row  = blockIdx.x * 8 + (threadIdx.x >> 5);
    const int lane = threadIdx.x & 31;
    float* p = out + (size_t)row * NEE;

    float vals[8];
    float m = -1e30f;
    #pragma unroll
    for (int i = 0; i < 8; i++) {
        vals[i] = p[i * 32 + lane];
        m = fmaxf(m, vals[i]);
    }
    #pragma unroll
    for (int s = 16; s > 0; s >>= 1) m = fmaxf(m, __shfl_xor_sync(0xFFFFFFFFu, m, s));

    float sum = 0.0f;
    #pragma unroll
    for (int i = 0; i < 8; i++) {
        vals[i] = __expf(vals[i] - m);
        sum += vals[i];
    }
    #pragma unroll
    for (int s = 16; s > 0; s >>= 1) sum += __shfl_xor_sync(0xFFFFFFFFu, sum, s);

    const float inv = 1.0f / sum;
    #pragma unroll
    for (int i = 0; i < 8; i++) p[i * 32 + lane] = vals[i] * inv;
}

// ---------------------------------------------------------------------------
extern "C" void kernel_launch(void* const* d_in, const int* in_sizes, int n_in,
                              void* d_out, int out_size)
{
    const int*   sents  = (const int*)  d_in[0];
    const int*   datas  = (const int*)  d_in[1];
    const int*   slab   = (const int*)  d_in[2];
    const int*   dlab   = (const int*)  d_in[3];
    const float* emb    = (const float*)d_in[6];
    const float* Wi_f   = (const float*)d_in[7];
    const float* Wh_f   = (const float*)d_in[8];
    const float* b_f    = (const float*)d_in[9];
    const float* Wi_b   = (const float*)d_in[10];
    const float* Wh_b   = (const float*)d_in[11];
    const float* b_b    = (const float*)d_in[12];
    const float* WiD_f  = (const float*)d_in[13];
    const float* WhD_f  = (const float*)d_in[14];
    const float* bD_f   = (const float*)d_in[15];
    const float* WiD_b  = (const float*)d_in[16];
    const float* WhD_b  = (const float*)d_in[17];
    const float* bD_b   = (const float*)d_in[18];
    const float* W1     = (const float*)d_in[19];
    const float* W2     = (const float*)d_in[20];
    const float* v      = (const float*)d_in[21];
    float* out = (float*)d_out;

    k_xw<<<dim3(NROW / 128, 4, 4), 256>>>(
        sents, datas, emb,
        Wi_f, b_f, Wi_b, b_b, WiD_f, bD_f, WiD_b, bD_b);

    k_lstm<<<dim3(BB, 4), 512>>>(Wh_f, Wh_b, WhD_f, WhD_b);

    k_ent<<<dim3(BB, 2), 128>>>(slab, dlab);

    k_encdec<<<dim3(NROW / 128, 2), 256>>>(W1, W2);

    k_logits<<<dim3(BB, NEE / 32, NEE / 64), 256>>>(v, out);

    k_softmax<<<(BB * NEE) / 8, 256>>>(out);
}

// round 12
// speedup vs baseline: 1.0743x; 1.0743x over previous
#include <cuda_runtime.h>

// Problem constants
#define BB   32
#define TT   256
#define ESZ  128
#define HH   64
#define H4   256
#define H2   128
#define UU   64
#define NEE  256
#define NROW (BB*TT)   // 8192

// Scratch (device globals: no allocations allowed)
__device__ float g_xw [4][NROW][H4];        // input projections + bias, per (net,dir)
__device__ float g_rnn[2][BB][TT][H2];      // bilstm outputs (concat fwd/bwd)
__device__ float g_ent[2][BB][NEE][H2];     // 0: wordent, 1: dataent
__device__ float g_enc[BB][NEE][UU];        // dataent @ W1^T
__device__ float g_dec[BB][NEE][UU];        // wordent @ W2^T

__device__ __forceinline__ float tanha(float x) {
    float y; asm("tanh.approx.f32 %0, %1;" : "=f"(y) : "f"(x)); return y;
}
__device__ __forceinline__ float siga(float x) {   // sigmoid via MUFU.TANH
    return 0.5f + 0.5f * tanha(0.5f * x);
}
__device__ __forceinline__ unsigned f2tf32(float x) {
    unsigned r; asm("cvt.rna.tf32.f32 %0, %1;" : "=r"(r) : "f"(x)); return r;
}
__device__ __forceinline__ void mma_tf32(
    float& c0, float& c1, float& c2, float& c3,
    unsigned a0, unsigned a1, unsigned a2, unsigned a3,
    unsigned b0, unsigned b1)
{
    asm volatile(
        "mma.sync.aligned.m16n8k8.row.col.f32.tf32.tf32.f32 "
        "{%0,%1,%2,%3}, {%4,%5,%6,%7}, {%8,%9}, {%0,%1,%2,%3};"
        : "+f"(c0), "+f"(c1), "+f"(c2), "+f"(c3)
        : "r"(a0), "r"(a1), "r"(a2), "r"(a3), "r"(b0), "r"(b1));
}

// Shared tile layout: rows padded to 36 floats (36*4=144B = 9*16B: float4-aligned,
// and frag loads (4g+q addressing) are bank-conflict-free).
#define KPAD 36

// ---------------------------------------------------------------------------
// K1: fused embedding gather + input GEMM via tf32 tensor cores (round-6 cfg):
//   g_xw[combo][row][col] = b[col] + emb[tok[row]] . Wi[col]
// Block tile 128 rows x 64 cols, K=128 in 32-chunks. 8 warps, each 32x32.
// grid: (NROW/128, 4, 4): x=rowblk, y=colblk, z=combo.
// ---------------------------------------------------------------------------
__global__ __launch_bounds__(256) void k_xw(
    const int* __restrict__ sents, const int* __restrict__ datas,
    const float* __restrict__ emb,
    const float* __restrict__ Wi0, const float* __restrict__ b0,
    const float* __restrict__ Wi1, const float* __restrict__ b1,
    const float* __restrict__ Wi2, const float* __restrict__ b2,
    const float* __restrict__ Wi3, const float* __restrict__ b3)
{
    const int combo = blockIdx.z;
    const float* Wi = (combo == 0) ? Wi0 : (combo == 1) ? Wi1 : (combo == 2) ? Wi2 : Wi3;
    const float* bv = (combo == 0) ? b0  : (combo == 1) ? b1  : (combo == 2) ? b2  : b3;
    const int* toks = (combo < 2) ? sents : datas;

    __shared__ float As[128][KPAD];
    __shared__ float Bs[64][KPAD];
    __shared__ int   stok[128];

    const int tid = threadIdx.x;
    const int rowbase = blockIdx.x * 128;
    const int colbase = blockIdx.y * 64;

    if (tid < 128) stok[tid] = toks[rowbase + tid];

    const int warp = tid >> 5;
    const int lane = tid & 31;
    const int wr = (warp >> 1) * 32;       // warp row offset within tile
    const int wc = (warp & 1) * 32;        // warp col offset within tile
    const int rg = lane >> 2;              // 0..7
    const int q  = lane & 3;               // 0..3

    float c[2][4][4];                       // [mtile][ntile][frag]
    #pragma unroll
    for (int mt = 0; mt < 2; mt++)
        #pragma unroll
        for (int nt = 0; nt < 4; nt++)
            #pragma unroll
            for (int i = 0; i < 4; i++) c[mt][nt][i] = 0.0f;

    __syncthreads();

    for (int ks = 0; ks < 128; ks += 32) {
        // Load A: 128 rows x 32 k = 1024 float4 / 256 thr = 4 each (gathered emb)
        #pragma unroll
        for (int i = 0; i < 4; i++) {
            int lin = i * 256 + tid;
            int r  = lin >> 3;            // 0..127
            int kq = lin & 7;             // 0..7
            float4 av = *(const float4*)&emb[(size_t)stok[r] * ESZ + ks + kq * 4];
            *(float4*)&As[r][kq * 4] = av;
        }
        // Load B: 64 cols x 32 k = 512 float4 / 256 thr = 2 each
        #pragma unroll
        for (int i = 0; i < 2; i++) {
            int lin = i * 256 + tid;
            int r  = lin >> 3;            // 0..63
            int kq = lin & 7;
            float4 wv = *(const float4*)&Wi[(size_t)(colbase + r) * ESZ + ks + kq * 4];
            *(float4*)&Bs[r][kq * 4] = wv;
        }
        __syncthreads();

        #pragma unroll
        for (int kk = 0; kk < 32; kk += 8) {
            unsigned a[2][4], b[4][2];
            #pragma unroll
            for (int mt = 0; mt < 2; mt++) {
                int r = wr + 16 * mt + rg;
                a[mt][0] = f2tf32(As[r    ][kk + q]);
                a[mt][1] = f2tf32(As[r + 8][kk + q]);
                a[mt][2] = f2tf32(As[r    ][kk + q + 4]);
                a[mt][3] = f2tf32(As[r + 8][kk + q + 4]);
            }
            #pragma unroll
            for (int nt = 0; nt < 4; nt++) {
                int n = wc + 8 * nt + rg;
                b[nt][0] = f2tf32(Bs[n][kk + q]);
                b[nt][1] = f2tf32(Bs[n][kk + q + 4]);
            }
            #pragma unroll
            for (int mt = 0; mt < 2; mt++)
                #pragma unroll
                for (int nt = 0; nt < 4; nt++)
                    mma_tf32(c[mt][nt][0], c[mt][nt][1], c[mt][nt][2], c[mt][nt][3],
                             a[mt][0], a[mt][1], a[mt][2], a[mt][3],
                             b[nt][0], b[nt][1]);
        }
        __syncthreads();
    }

    // Epilogue: add bias, write g_xw
    #pragma unroll
    for (int mt = 0; mt < 2; mt++) {
        int r = rowbase + wr + 16 * mt + rg;
        #pragma unroll
        for (int nt = 0; nt < 4; nt++) {
            int col = colbase + wc + 8 * nt + 2 * q;
            float bx = bv[col], by = bv[col + 1];
            float2 v0 = make_float2(c[mt][nt][0] + bx, c[mt][nt][1] + by);
            float2 v1 = make_float2(c[mt][nt][2] + bx, c[mt][nt][3] + by);
            *(float2*)&g_xw[combo][r    ][col] = v0;
            *(float2*)&g_xw[combo][r + 8][col] = v1;
        }
    }
}

// ---------------------------------------------------------------------------
// K2: LSTM recurrence (round-6 version — best measured across 5 variants).
// One block per (b, combo). 256 threads: thread j owns z_j (Wh row j in
// registers, 4-way split accumulators). Threads 0..63 own gate/state updates.
// Next-step xw prefetched; activations via MUFU.TANH.
// ---------------------------------------------------------------------------
__global__ __launch_bounds__(256) void k_lstm(
    const float* __restrict__ Wh0, const float* __restrict__ Wh1,
    const float* __restrict__ Wh2, const float* __restrict__ Wh3)
{
    const int b = blockIdx.x;
    const int combo = blockIdx.y;
    const int net = combo >> 1;
    const int dir = combo & 1;
    const float* Wh = (combo == 0) ? Wh0 : (combo == 1) ? Wh1 : (combo == 2) ? Wh2 : Wh3;

    const int j = threadIdx.x;
    float wh[64];
    #pragma unroll
    for (int k4 = 0; k4 < 16; k4++) {
        float4 t4 = *(const float4*)&Wh[(size_t)j * HH + k4 * 4];
        wh[k4*4+0] = t4.x; wh[k4*4+1] = t4.y; wh[k4*4+2] = t4.z; wh[k4*4+3] = t4.w;
    }

    __shared__ __align__(16) float h_s[HH];
    __shared__ float z_s[H4];
    float cst = 0.0f;
    if (j < HH) h_s[j] = 0.0f;

    const float* xwp = &g_xw[combo][b * TT][0];
    const int tstep = dir ? -1 : 1;
    int t = dir ? (TT - 1) : 0;
    float xcur = xwp[t * H4 + j];
    __syncthreads();

    for (int ti = 0; ti < TT; ti++) {
        float xnext = (ti + 1 < TT) ? xwp[(t + tstep) * H4 + j] : 0.0f;

        float a0 = xcur, a1 = 0.0f, a2 = 0.0f, a3 = 0.0f;
        #pragma unroll
        for (int k4 = 0; k4 < 16; k4 += 4) {
            float4 h0 = ((const float4*)h_s)[k4 + 0];
            float4 h1 = ((const float4*)h_s)[k4 + 1];
            float4 h2 = ((const float4*)h_s)[k4 + 2];
            float4 h3 = ((const float4*)h_s)[k4 + 3];
            a0 = fmaf(wh[(k4+0)*4+0], h0.x, a0);
            a0 = fmaf(wh[(k4+0)*4+1], h0.y, a0);
            a0 = fmaf(wh[(k4+0)*4+2], h0.z, a0);
            a0 = fmaf(wh[(k4+0)*4+3], h0.w, a0);
            a1 = fmaf(wh[(k4+1)*4+0], h1.x, a1);
            a1 = fmaf(wh[(k4+1)*4+1], h1.y, a1);
            a1 = fmaf(wh[(k4+1)*4+2], h1.z, a1);
            a1 = fmaf(wh[(k4+1)*4+3], h1.w, a1);
            a2 = fmaf(wh[(k4+2)*4+0], h2.x, a2);
            a2 = fmaf(wh[(k4+2)*4+1], h2.y, a2);
            a2 = fmaf(wh[(k4+2)*4+2], h2.z, a2);
            a2 = fmaf(wh[(k4+2)*4+3], h2.w, a2);
            a3 = fmaf(wh[(k4+3)*4+0], h3.x, a3);
            a3 = fmaf(wh[(k4+3)*4+1], h3.y, a3);
            a3 = fmaf(wh[(k4+3)*4+2], h3.z, a3);
            a3 = fmaf(wh[(k4+3)*4+3], h3.w, a3);
        }
        z_s[j] = (a0 + a1) + (a2 + a3);
        __syncthreads();
        if (j < HH) {
            float iv = siga(z_s[j]);
            float fv = siga(z_s[j + HH]);
            float gv = tanha(z_s[j + 2*HH]);
            float ov = siga(z_s[j + 3*HH]);
            cst = fv * cst + iv * gv;
            float hv = ov * tanha(cst);
            h_s[j] = hv;
            g_rnn[net][b][t][dir * HH + j] = hv;
        }
        __syncthreads();
        xcur = xnext;
        t += tstep;
    }
}

// ---------------------------------------------------------------------------
// K3: entity extraction (segment means). One block per (b, which).
// ---------------------------------------------------------------------------
__global__ __launch_bounds__(128) void k_ent(
    const int* __restrict__ slab, const int* __restrict__ dlab)
{
    const int b = blockIdx.x;
    const int which = blockIdx.y;
    const int* lab = which ? dlab : slab;

    __shared__ int s_eid[TT];
    __shared__ int s_cnt[TT];
    __shared__ int s_closed;

    const int f = threadIdx.x;
    s_cnt[f] = 0; s_cnt[f + 128] = 0;
    __syncthreads();

    if (f == 0) {
        bool st = false; int ne = 0;
        for (int t = 0; t < TT; t++) {
            int l = lab[b * TT + t];
            if (l == 1)      { st = true; ne++; }
            else if (l == 0) { st = false; }
            if (st) { s_eid[t] = ne - 1; s_cnt[ne - 1]++; }
            else    { s_eid[t] = -1; }
        }
        s_closed = ne - (st ? 1 : 0);
    }
    __syncthreads();

    const int closed = s_closed;
    float* dst = &g_ent[which][b][0][0];
    for (int e = 0; e < NEE; e++) dst[e * H2 + f] = 0.0f;

    const float* src = &g_rnn[which][b][0][0];
    float acc = 0.0f; int cur = -1;
    for (int t = 0; t < TT; t++) {
        int e = s_eid[t];
        if (e != cur) {
            if (cur >= 0 && cur < closed) dst[cur * H2 + f] = acc / (float)s_cnt[cur];
            acc = 0.0f; cur = e;
        }
        if (e >= 0) acc += src[t * H2 + f];
    }
    if (cur >= 0 && cur < closed) dst[cur * H2 + f] = acc / (float)s_cnt[cur];
}

// ---------------------------------------------------------------------------
// K4: enc/dec projections via tf32 tensor cores.
// z=0: g_enc = dataent @ W1^T; z=1: g_dec = wordent @ W2^T
// Block tile 128 rows x 64 cols (full N), K=128 in 32-chunks. grid (64, 2).
// ---------------------------------------------------------------------------
__global__ __launch_bounds__(256) void k_encdec(
    const float* __restrict__ W1, const float* __restrict__ W2)
{
    const int z = blockIdx.y;
    const float* src = (z == 0) ? &g_ent[1][0][0][0] : &g_ent[0][0][0][0];
    const float* W   = (z == 0) ? W1 : W2;
    float* dst       = (z == 0) ? &g_enc[0][0][0] : &g_dec[0][0][0];

    __shared__ float As[128][KPAD];
    __shared__ float Bs[64][KPAD];

    const int tid = threadIdx.x;
    const int rowbase = blockIdx.x * 128;

    const int warp = tid >> 5;
    const int lane = tid & 31;
    const int wr = (warp >> 1) * 32;
    const int wc = (warp & 1) * 32;
    const int rg = lane >> 2;
    const int q  = lane & 3;

    float c[2][4][4];
    #pragma unroll
    for (int mt = 0; mt < 2; mt++)
        #pragma unroll
        for (int nt = 0; nt < 4; nt++)
            #pragma unroll
            for (int i = 0; i < 4; i++) c[mt][nt][i] = 0.0f;

    for (int ks = 0; ks < 128; ks += 32) {
        #pragma unroll
        for (int i = 0; i < 4; i++) {
            int lin = i * 256 + tid;
            int r  = lin >> 3;
            int kq = lin & 7;
            float4 av = *(const float4*)&src[(size_t)(rowbase + r) * H2 + ks + kq * 4];
            *(float4*)&As[r][kq * 4] = av;
        }
        #pragma unroll
        for (int i = 0; i < 2; i++) {
            int lin = i * 256 + tid;
            int r  = lin >> 3;
            int kq = lin & 7;
            float4 wv = *(const float4*)&W[(size_t)r * H2 + ks + kq * 4];
            *(float4*)&Bs[r][kq * 4] = wv;
        }
        __syncthreads();

        #pragma unroll
        for (int kk = 0; kk < 32; kk += 8) {
            unsigned a[2][4], b[4][2];
            #pragma unroll
            for (int mt = 0; mt < 2; mt++) {
                int r = wr + 16 * mt + rg;
                a[mt][0] = f2tf32(As[r    ][kk + q]);
                a[mt][1] = f2tf32(As[r + 8][kk + q]);
                a[mt][2] = f2tf32(As[r    ][kk + q + 4]);
                a[mt][3] = f2tf32(As[r + 8][kk + q + 4]);
            }
            #pragma unroll
            for (int nt = 0; nt < 4; nt++) {
                int n = wc + 8 * nt + rg;
                b[nt][0] = f2tf32(Bs[n][kk + q]);
                b[nt][1] = f2tf32(Bs[n][kk + q + 4]);
            }
            #pragma unroll
            for (int mt = 0; mt < 2; mt++)
                #pragma unroll
                for (int nt = 0; nt < 4; nt++)
                    mma_tf32(c[mt][nt][0], c[mt][nt][1], c[mt][nt][2], c[mt][nt][3],
                             a[mt][0], a[mt][1], a[mt][2], a[mt][3],
                             b[nt][0], b[nt][1]);
        }
        __syncthreads();
    }

    #pragma unroll
    for (int mt = 0; mt < 2; mt++) {
        int r = rowbase + wr + 16 * mt + rg;
        #pragma unroll
        for (int nt = 0; nt < 4; nt++) {
            int col = wc + 8 * nt + 2 * q;
            *(float2*)&dst[(size_t)r * UU + col] =
                make_float2(c[mt][nt][0], c[mt][nt][1]);
            *(float2*)&dst[(size_t)(r + 8) * UU + col] =
                make_float2(c[mt][nt][2], c[mt][nt][3]);
        }
    }
}

// ---------------------------------------------------------------------------
// K5: fused logits + softmax.
// logits[b][w][d] = sum_u v[u] * tanh(enc[b][d][u] + dec[b][w][u]);
// out[b][w][:] = softmax_d(logits).
// Block per (b, 32-w tile); loops 4 enc d-tiles of 64, keeping all 256
// logits in registers (32/thread: thread (wloc,dg) owns d = dt*64 + 8j + dg).
// Row softmax reduced via shfl_xor within each 8-lane dg-group.
// ---------------------------------------------------------------------------
__global__ __launch_bounds__(256) void k_logits_sm(
    const float* __restrict__ v, float* __restrict__ out)
{
    const int b = blockIdx.x, wt = blockIdx.y;

    __shared__ float enc_s[64][68];
    __shared__ float dec_s[32][68];
    __shared__ __align__(16) float v_s[64];

    const int tid = threadIdx.x;
    if (tid < 64) v_s[tid] = v[tid];

    #pragma unroll
    for (int i = 0; i < 2; i++) {
        int lin = i * 256 + tid;
        int w = lin >> 4, u4 = lin & 15;
        float4 val = *(const float4*)&g_dec[b][wt * 32 + w][u4 * 4];
        *(float4*)&dec_s[w][u4 * 4] = val;
    }

    const int wloc = tid >> 3;     // 0..31
    const int dg   = tid & 7;      // 0..7
    float acc[4][8];

    for (int dt = 0; dt < 4; dt++) {
        __syncthreads();
        #pragma unroll
        for (int i = 0; i < 4; i++) {
            int lin = i * 256 + tid;
            int d = lin >> 4, u4 = lin & 15;
            float4 val = *(const float4*)&g_enc[b][dt * 64 + d][u4 * 4];
            *(float4*)&enc_s[d][u4 * 4] = val;
        }
        __syncthreads();

        #pragma unroll
        for (int jj = 0; jj < 8; jj++) acc[dt][jj] = 0.0f;

        #pragma unroll
        for (int u4 = 0; u4 < 16; u4++) {
            float4 dv = *(const float4*)&dec_s[wloc][u4 * 4];
            float4 vv = *(const float4*)&v_s[u4 * 4];
            #pragma unroll
            for (int jj = 0; jj < 8; jj++) {
                float4 ev = *(const float4*)&enc_s[dg + 8 * jj][u4 * 4];
                acc[dt][jj] = fmaf(vv.x, tanha(ev.x + dv.x), acc[dt][jj]);
                acc[dt][jj] = fmaf(vv.y, tanha(ev.y + dv.y), acc[dt][jj]);
                acc[dt][jj] = fmaf(vv.z, tanha(ev.z + dv.z), acc[dt][jj]);
                acc[dt][jj] = fmaf(vv.w, tanha(ev.w + dv.w), acc[dt][jj]);
            }
        }
    }

    // Softmax over the 256 d's of row w = wt*32 + wloc (held across the
    // 8 lanes with the same wloc; lane xor 1,2,4 stays in the dg-group).
    float m = -1e30f;
    #pragma unroll
    for (int dt = 0; dt < 4; dt++)
        #pragma unroll
        for (int jj = 0; jj < 8; jj++) m = fmaxf(m, acc[dt][jj]);
    #pragma unroll
    for (int s = 1; s < 8; s <<= 1) m = fmaxf(m, __shfl_xor_sync(0xFFFFFFFFu, m, s));

    float sum = 0.0f;
    #pragma unroll
    for (int dt = 0; dt < 4; dt++)
        #pragma unroll
        for (int jj = 0; jj < 8; jj++) {
            acc[dt][jj] = __expf(acc[dt][jj] - m);
            sum += acc[dt][jj];
        }
    #pragma unroll
    for (int s = 1; s < 8; s <<= 1) sum += __shfl_xor_sync(0xFFFFFFFFu, sum, s);
    const float inv = 1.0f / sum;

    const int w = wt * 32 + wloc;
    float* op = out + ((size_t)b * NEE + w) * NEE;
    #pragma unroll
    for (int dt = 0; dt < 4; dt++)
        #pragma unroll
        for (int jj = 0; jj < 8; jj++)
            op[dt * 64 + 8 * jj + dg] = acc[dt][jj] * inv;
}

// ---------------------------------------------------------------------------
extern "C" void kernel_launch(void* const* d_in, const int* in_sizes, int n_in,
                              void* d_out, int out_size)
{
    const int*   sents  = (const int*)  d_in[0];
    const int*   datas  = (const int*)  d_in[1];
    const int*   slab   = (const int*)  d_in[2];
    const int*   dlab   = (const int*)  d_in[3];
    const float* emb    = (const float*)d_in[6];
    const float* Wi_f   = (const float*)d_in[7];
    const float* Wh_f   = (const float*)d_in[8];
    const float* b_f    = (const float*)d_in[9];
    const float* Wi_b   = (const float*)d_in[10];
    const float* Wh_b   = (const float*)d_in[11];
    const float* b_b    = (const float*)d_in[12];
    const float* WiD_f  = (const float*)d_in[13];
    const float* WhD_f  = (const float*)d_in[14];
    const float* bD_f   = (const float*)d_in[15];
    const float* WiD_b  = (const float*)d_in[16];
    const float* WhD_b  = (const float*)d_in[17];
    const float* bD_b   = (const float*)d_in[18];
    const float* W1     = (const float*)d_in[19];
    const float* W2     = (const float*)d_in[20];
    const float* v      = (const float*)d_in[21];
    float* out = (float*)d_out;

    k_xw<<<dim3(NROW / 128, 4, 4), 256>>>(
        sents, datas, emb,
        Wi_f, b_f, Wi_b, b_b, WiD_f, bD_f, WiD_b, bD_b);

    k_lstm<<<dim3(BB, 4), 256>>>(Wh_f, Wh_b, WhD_f, WhD_b);

    k_ent<<<dim3(BB, 2), 128>>>(slab, dlab);

    k_encdec<<<dim3(NROW / 128, 2), 256>>>(W1, W2);

    k_logits_sm<<<dim3(BB, NEE / 32), 256>>>(v, out);
}

// round 14
// speedup vs baseline: 1.1054x; 1.0290x over previous
#include <cuda_runtime.h>

// Problem constants
#define BB   32
#define TT   256
#define ESZ  128
#define HH   64
#define H4   256
#define H2   128
#define UU   64
#define NEE  256
#define NROW (BB*TT)   // 8192

// Scratch (device globals: no allocations allowed)
__device__ float g_xw [4][NROW][H4];        // input projections + bias, per (net,dir)
__device__ float g_rnn[2][BB][TT][H2];      // bilstm outputs (concat fwd/bwd)
__device__ float g_ent[2][BB][NEE][H2];     // 0: wordent, 1: dataent
__device__ float g_enc[BB][NEE][UU];        // dataent @ W1^T
__device__ float g_dec[BB][NEE][UU];        // wordent @ W2^T

__device__ __forceinline__ float tanha(float x) {
    float y; asm("tanh.approx.f32 %0, %1;" : "=f"(y) : "f"(x)); return y;
}
__device__ __forceinline__ float siga(float x) {   // sigmoid via MUFU.TANH
    return 0.5f + 0.5f * tanha(0.5f * x);
}
__device__ __forceinline__ unsigned f2tf32(float x) {
    unsigned r; asm("cvt.rna.tf32.f32 %0, %1;" : "=r"(r) : "f"(x)); return r;
}
__device__ __forceinline__ void mma_tf32(
    float& c0, float& c1, float& c2, float& c3,
    unsigned a0, unsigned a1, unsigned a2, unsigned a3,
    unsigned b0, unsigned b1)
{
    asm volatile(
        "mma.sync.aligned.m16n8k8.row.col.f32.tf32.tf32.f32 "
        "{%0,%1,%2,%3}, {%4,%5,%6,%7}, {%8,%9}, {%0,%1,%2,%3};"
        : "+f"(c0), "+f"(c1), "+f"(c2), "+f"(c3)
        : "r"(a0), "r"(a1), "r"(a2), "r"(a3), "r"(b0), "r"(b1));
}

// Shared tile layout: rows padded to 36 floats (36*4=144B = 9*16B: float4-aligned,
// and frag loads (4g+q addressing) are bank-conflict-free).
#define KPAD 36

// ---------------------------------------------------------------------------
// K1: fused embedding gather + input GEMM via tf32 tensor cores:
//   g_xw[combo][row][col] = b[col] + emb[tok[row]] . Wi[col]
// Block tile 128 rows x 64 cols, K=128 in 32-chunks. 8 warps, each 32x32.
// grid: (NROW/128, 4, 4): x=rowblk, y=colblk, z=combo.
// ---------------------------------------------------------------------------
__global__ __launch_bounds__(256) void k_xw(
    const int* __restrict__ sents, const int* __restrict__ datas,
    const float* __restrict__ emb,
    const float* __restrict__ Wi0, const float* __restrict__ b0,
    const float* __restrict__ Wi1, const float* __restrict__ b1,
    const float* __restrict__ Wi2, const float* __restrict__ b2,
    const float* __restrict__ Wi3, const float* __restrict__ b3)
{
    const int combo = blockIdx.z;
    const float* Wi = (combo == 0) ? Wi0 : (combo == 1) ? Wi1 : (combo == 2) ? Wi2 : Wi3;
    const float* bv = (combo == 0) ? b0  : (combo == 1) ? b1  : (combo == 2) ? b2  : b3;
    const int* toks = (combo < 2) ? sents : datas;

    __shared__ float As[128][KPAD];
    __shared__ float Bs[64][KPAD];
    __shared__ int   stok[128];

    const int tid = threadIdx.x;
    const int rowbase = blockIdx.x * 128;
    const int colbase = blockIdx.y * 64;

    if (tid < 128) stok[tid] = toks[rowbase + tid];

    const int warp = tid >> 5;
    const int lane = tid & 31;
    const int wr = (warp >> 1) * 32;       // warp row offset within tile
    const int wc = (warp & 1) * 32;        // warp col offset within tile
    const int rg = lane >> 2;              // 0..7
    const int q  = lane & 3;               // 0..3

    float c[2][4][4];                       // [mtile][ntile][frag]
    #pragma unroll
    for (int mt = 0; mt < 2; mt++)
        #pragma unroll
        for (int nt = 0; nt < 4; nt++)
            #pragma unroll
            for (int i = 0; i < 4; i++) c[mt][nt][i] = 0.0f;

    __syncthreads();

    for (int ks = 0; ks < 128; ks += 32) {
        // Load A: 128 rows x 32 k = 1024 float4 / 256 thr = 4 each (gathered emb)
        #pragma unroll
        for (int i = 0; i < 4; i++) {
            int lin = i * 256 + tid;
            int r  = lin >> 3;            // 0..127
            int kq = lin & 7;             // 0..7
            float4 av = *(const float4*)&emb[(size_t)stok[r] * ESZ + ks + kq * 4];
            *(float4*)&As[r][kq * 4] = av;
        }
        // Load B: 64 cols x 32 k = 512 float4 / 256 thr = 2 each
        #pragma unroll
        for (int i = 0; i < 2; i++) {
            int lin = i * 256 + tid;
            int r  = lin >> 3;            // 0..63
            int kq = lin & 7;
            float4 wv = *(const float4*)&Wi[(size_t)(colbase + r) * ESZ + ks + kq * 4];
            *(float4*)&Bs[r][kq * 4] = wv;
        }
        __syncthreads();

        #pragma unroll
        for (int kk = 0; kk < 32; kk += 8) {
            unsigned a[2][4], b[4][2];
            #pragma unroll
            for (int mt = 0; mt < 2; mt++) {
                int r = wr + 16 * mt + rg;
                a[mt][0] = f2tf32(As[r    ][kk + q]);
                a[mt][1] = f2tf32(As[r + 8][kk + q]);
                a[mt][2] = f2tf32(As[r    ][kk + q + 4]);
                a[mt][3] = f2tf32(As[r + 8][kk + q + 4]);
            }
            #pragma unroll
            for (int nt = 0; nt < 4; nt++) {
                int n = wc + 8 * nt + rg;
                b[nt][0] = f2tf32(Bs[n][kk + q]);
                b[nt][1] = f2tf32(Bs[n][kk + q + 4]);
            }
            #pragma unroll
            for (int mt = 0; mt < 2; mt++)
                #pragma unroll
                for (int nt = 0; nt < 4; nt++)
                    mma_tf32(c[mt][nt][0], c[mt][nt][1], c[mt][nt][2], c[mt][nt][3],
                             a[mt][0], a[mt][1], a[mt][2], a[mt][3],
                             b[nt][0], b[nt][1]);
        }
        __syncthreads();
    }

    // Epilogue: add bias, write g_xw
    #pragma unroll
    for (int mt = 0; mt < 2; mt++) {
        int r = rowbase + wr + 16 * mt + rg;
        #pragma unroll
        for (int nt = 0; nt < 4; nt++) {
            int col = colbase + wc + 8 * nt + 2 * q;
            float bx = bv[col], by = bv[col + 1];
            float2 v0 = make_float2(c[mt][nt][0] + bx, c[mt][nt][1] + by);
            float2 v1 = make_float2(c[mt][nt][2] + bx, c[mt][nt][3] + by);
            *(float2*)&g_xw[combo][r    ][col] = v0;
            *(float2*)&g_xw[combo][r + 8][col] = v1;
        }
    }
}

// ---------------------------------------------------------------------------
// K2: LSTM recurrence (best measured across 5 structural variants).
// One block per (b, combo). 256 threads: thread j owns z_j (Wh row j in
// registers, 4-way split accumulators). Threads 0..63 own gate/state updates.
// Next-step xw prefetched; activations via MUFU.TANH.
// ---------------------------------------------------------------------------
__global__ __launch_bounds__(256) void k_lstm(
    const float* __restrict__ Wh0, const float* __restrict__ Wh1,
    const float* __restrict__ Wh2, const float* __restrict__ Wh3)
{
    const int b = blockIdx.x;
    const int combo = blockIdx.y;
    const int net = combo >> 1;
    const int dir = combo & 1;
    const float* Wh = (combo == 0) ? Wh0 : (combo == 1) ? Wh1 : (combo == 2) ? Wh2 : Wh3;

    const int j = threadIdx.x;
    float wh[64];
    #pragma unroll
    for (int k4 = 0; k4 < 16; k4++) {
        float4 t4 = *(const float4*)&Wh[(size_t)j * HH + k4 * 4];
        wh[k4*4+0] = t4.x; wh[k4*4+1] = t4.y; wh[k4*4+2] = t4.z; wh[k4*4+3] = t4.w;
    }

    __shared__ __align__(16) float h_s[HH];
    __shared__ float z_s[H4];
    float cst = 0.0f;
    if (j < HH) h_s[j] = 0.0f;

    const float* xwp = &g_xw[combo][b * TT][0];
    const int tstep = dir ? -1 : 1;
    int t = dir ? (TT - 1) : 0;
    float xcur = xwp[t * H4 + j];
    __syncthreads();

    for (int ti = 0; ti < TT; ti++) {
        float xnext = (ti + 1 < TT) ? xwp[(t + tstep) * H4 + j] : 0.0f;

        float a0 = xcur, a1 = 0.0f, a2 = 0.0f, a3 = 0.0f;
        #pragma unroll
        for (int k4 = 0; k4 < 16; k4 += 4) {
            float4 h0 = ((const float4*)h_s)[k4 + 0];
            float4 h1 = ((const float4*)h_s)[k4 + 1];
            float4 h2 = ((const float4*)h_s)[k4 + 2];
            float4 h3 = ((const float4*)h_s)[k4 + 3];
            a0 = fmaf(wh[(k4+0)*4+0], h0.x, a0);
            a0 = fmaf(wh[(k4+0)*4+1], h0.y, a0);
            a0 = fmaf(wh[(k4+0)*4+2], h0.z, a0);
            a0 = fmaf(wh[(k4+0)*4+3], h0.w, a0);
            a1 = fmaf(wh[(k4+1)*4+0], h1.x, a1);
            a1 = fmaf(wh[(k4+1)*4+1], h1.y, a1);
            a1 = fmaf(wh[(k4+1)*4+2], h1.z, a1);
            a1 = fmaf(wh[(k4+1)*4+3], h1.w, a1);
            a2 = fmaf(wh[(k4+2)*4+0], h2.x, a2);
            a2 = fmaf(wh[(k4+2)*4+1], h2.y, a2);
            a2 = fmaf(wh[(k4+2)*4+2], h2.z, a2);
            a2 = fmaf(wh[(k4+2)*4+3], h2.w, a2);
            a3 = fmaf(wh[(k4+3)*4+0], h3.x, a3);
            a3 = fmaf(wh[(k4+3)*4+1], h3.y, a3);
            a3 = fmaf(wh[(k4+3)*4+2], h3.z, a3);
            a3 = fmaf(wh[(k4+3)*4+3], h3.w, a3);
        }
        z_s[j] = (a0 + a1) + (a2 + a3);
        __syncthreads();
        if (j < HH) {
            float iv = siga(z_s[j]);
            float fv = siga(z_s[j + HH]);
            float gv = tanha(z_s[j + 2*HH]);
            float ov = siga(z_s[j + 3*HH]);
            cst = fv * cst + iv * gv;
            float hv = ov * tanha(cst);
            h_s[j] = hv;
            g_rnn[net][b][t][dir * HH + j] = hv;
        }
        __syncthreads();
        xcur = xnext;
        t += tstep;
    }
}

// ---------------------------------------------------------------------------
// K3: entity extraction (segment means). One block per (b, which).
// ---------------------------------------------------------------------------
__global__ __launch_bounds__(128) void k_ent(
    const int* __restrict__ slab, const int* __restrict__ dlab)
{
    const int b = blockIdx.x;
    const int which = blockIdx.y;
    const int* lab = which ? dlab : slab;

    __shared__ int s_eid[TT];
    __shared__ int s_cnt[TT];
    __shared__ int s_closed;

    const int f = threadIdx.x;
    s_cnt[f] = 0; s_cnt[f + 128] = 0;
    __syncthreads();

    if (f == 0) {
        bool st = false; int ne = 0;
        for (int t = 0; t < TT; t++) {
            int l = lab[b * TT + t];
            if (l == 1)      { st = true; ne++; }
            else if (l == 0) { st = false; }
            if (st) { s_eid[t] = ne - 1; s_cnt[ne - 1]++; }
            else    { s_eid[t] = -1; }
        }
        s_closed = ne - (st ? 1 : 0);
    }
    __syncthreads();

    const int closed = s_closed;
    float* dst = &g_ent[which][b][0][0];
    for (int e = 0; e < NEE; e++) dst[e * H2 + f] = 0.0f;

    const float* src = &g_rnn[which][b][0][0];
    float acc = 0.0f; int cur = -1;
    for (int t = 0; t < TT; t++) {
        int e = s_eid[t];
        if (e != cur) {
            if (cur >= 0 && cur < closed) dst[cur * H2 + f] = acc / (float)s_cnt[cur];
            acc = 0.0f; cur = e;
        }
        if (e >= 0) acc += src[t * H2 + f];
    }
    if (cur >= 0 && cur < closed) dst[cur * H2 + f] = acc / (float)s_cnt[cur];
}

// ---------------------------------------------------------------------------
// K4: enc/dec projections via tf32 tensor cores.
// z=0: g_enc = dataent @ W1^T; z=1: g_dec = wordent @ W2^T
// Block tile 128 rows x 64 cols (full N), K=128 in 32-chunks. grid (64, 2).
// ---------------------------------------------------------------------------
__global__ __launch_bounds__(256) void k_encdec(
    const float* __restrict__ W1, const float* __restrict__ W2)
{
    const int z = blockIdx.y;
    const float* src = (z == 0) ? &g_ent[1][0][0][0] : &g_ent[0][0][0][0];
    const float* W   = (z == 0) ? W1 : W2;
    float* dst       = (z == 0) ? &g_enc[0][0][0] : &g_dec[0][0][0];

    __shared__ float As[128][KPAD];
    __shared__ float Bs[64][KPAD];

    const int tid = threadIdx.x;
    const int rowbase = blockIdx.x * 128;

    const int warp = tid >> 5;
    const int lane = tid & 31;
    const int wr = (warp >> 1) * 32;
    const int wc = (warp & 1) * 32;
    const int rg = lane >> 2;
    const int q  = lane & 3;

    float c[2][4][4];
    #pragma unroll
    for (int mt = 0; mt < 2; mt++)
        #pragma unroll
        for (int nt = 0; nt < 4; nt++)
            #pragma unroll
            for (int i = 0; i < 4; i++) c[mt][nt][i] = 0.0f;

    for (int ks = 0; ks < 128; ks += 32) {
        #pragma unroll
        for (int i = 0; i < 4; i++) {
            int lin = i * 256 + tid;
            int r  = lin >> 3;
            int kq = lin & 7;
            float4 av = *(const float4*)&src[(size_t)(rowbase + r) * H2 + ks + kq * 4];
            *(float4*)&As[r][kq * 4] = av;
        }
        #pragma unroll
        for (int i = 0; i < 2; i++) {
            int lin = i * 256 + tid;
            int r  = lin >> 3;
            int kq = lin & 7;
            float4 wv = *(const float4*)&W[(size_t)r * H2 + ks + kq * 4];
            *(float4*)&Bs[r][kq * 4] = wv;
        }
        __syncthreads();

        #pragma unroll
        for (int kk = 0; kk < 32; kk += 8) {
            unsigned a[2][4], b[4][2];
            #pragma unroll
            for (int mt = 0; mt < 2; mt++) {
                int r = wr + 16 * mt + rg;
                a[mt][0] = f2tf32(As[r    ][kk + q]);
                a[mt][1] = f2tf32(As[r + 8][kk + q]);
                a[mt][2] = f2tf32(As[r    ][kk + q + 4]);
                a[mt][3] = f2tf32(As[r + 8][kk + q + 4]);
            }
            #pragma unroll
            for (int nt = 0; nt < 4; nt++) {
                int n = wc + 8 * nt + rg;
                b[nt][0] = f2tf32(Bs[n][kk + q]);
                b[nt][1] = f2tf32(Bs[n][kk + q + 4]);
            }
            #pragma unroll
            for (int mt = 0; mt < 2; mt++)
                #pragma unroll
                for (int nt = 0; nt < 4; nt++)
                    mma_tf32(c[mt][nt][0], c[mt][nt][1], c[mt][nt][2], c[mt][nt][3],
                             a[mt][0], a[mt][1], a[mt][2], a[mt][3],
                             b[nt][0], b[nt][1]);
        }
        __syncthreads();
    }

    #pragma unroll
    for (int mt = 0; mt < 2; mt++) {
        int r = rowbase + wr + 16 * mt + rg;
        #pragma unroll
        for (int nt = 0; nt < 4; nt++) {
            int col = wc + 8 * nt + 2 * q;
            *(float2*)&dst[(size_t)r * UU + col] =
                make_float2(c[mt][nt][0], c[mt][nt][1]);
            *(float2*)&dst[(size_t)(r + 8) * UU + col] =
                make_float2(c[mt][nt][2], c[mt][nt][3]);
        }
    }
}

// ---------------------------------------------------------------------------
// K5: logits[b][w][d] = sum_u v[u] * tanh(enc[b][d][u] + dec[b][w][u])
// Block: (b, 32-w tile, 64-d tile). Hardware tanh.approx (MUFU.TANH).
// Kept SEPARATE from softmax: the fused variant measured +7 us (occupancy
// loss outweighs the saved logits round-trip).
// ---------------------------------------------------------------------------
__global__ __launch_bounds__(256) void k_logits(
    const float* __restrict__ v, float* __restrict__ out)
{
    const int b = blockIdx.x, wt = blockIdx.y, dt = blockIdx.z;

    __shared__ float enc_s[64][68];
    __shared__ float dec_s[32][68];
    __shared__ __align__(16) float v_s[64];

    const int tid = threadIdx.x;
    if (tid < 64) v_s[tid] = v[tid];

    #pragma unroll
    for (int i = 0; i < 4; i++) {
        int lin = i * 256 + tid;
        int d = lin >> 4, u4 = lin & 15;
        float4 val = *(const float4*)&g_enc[b][dt * 64 + d][u4 * 4];
        *(float4*)&enc_s[d][u4 * 4] = val;
    }
    #pragma unroll
    for (int i = 0; i < 2; i++) {
        int lin = i * 256 + tid;
        int w = lin >> 4, u4 = lin & 15;
        float4 val = *(const float4*)&g_dec[b][wt * 32 + w][u4 * 4];
        *(float4*)&dec_s[w][u4 * 4] = val;
    }
    __syncthreads();

    const int wloc = tid >> 3;     // 0..31
    const int dg   = tid & 7;      // 0..7
    float acc[8] = {0.f, 0.f, 0.f, 0.f, 0.f, 0.f, 0.f, 0.f};

    #pragma unroll
    for (int u4 = 0; u4 < 16; u4++) {
        float4 dv = *(const float4*)&dec_s[wloc][u4 * 4];
        float4 vv = *(const float4*)&v_s[u4 * 4];
        #pragma unroll
        for (int jj = 0; jj < 8; jj++) {
            float4 ev = *(const float4*)&enc_s[dg + 8 * jj][u4 * 4];
            acc[jj] = fmaf(vv.x, tanha(ev.x + dv.x), acc[jj]);
            acc[jj] = fmaf(vv.y, tanha(ev.y + dv.y), acc[jj]);
            acc[jj] = fmaf(vv.z, tanha(ev.z + dv.z), acc[jj]);
            acc[jj] = fmaf(vv.w, tanha(ev.w + dv.w), acc[jj]);
        }
    }

    const int w = wt * 32 + wloc;
    float* op = out + ((size_t)b * NEE + w) * NEE + dt * 64;
    #pragma unroll
    for (int jj = 0; jj < 8; jj++) op[dg + 8 * jj] = acc[jj];
}

// ---------------------------------------------------------------------------
// K6: in-place row softmax over last dim (256). One warp per row.
// ---------------------------------------------------------------------------
__global__ __launch_bounds__(256) void k_softmax(float* __restrict__ out)
{
    const int row  = blockIdx.x * 8 + (threadIdx.x >> 5);
    const int lane = threadIdx.x & 31;
    float* p = out + (size_t)row * NEE;

    float vals[8];
    float m = -1e30f;
    #pragma unroll
    for (int i = 0; i < 8; i++) {
        vals[i] = p[i * 32 + lane];
        m = fmaxf(m, vals[i]);
    }
    #pragma unroll
    for (int s = 16; s > 0; s >>= 1) m = fmaxf(m, __shfl_xor_sync(0xFFFFFFFFu, m, s));

    float sum = 0.0f;
    #pragma unroll
    for (int i = 0; i < 8; i++) {
        vals[i] = __expf(vals[i] - m);
        sum += vals[i];
    }
    #pragma unroll
    for (int s = 16; s > 0; s >>= 1) sum += __shfl_xor_sync(0xFFFFFFFFu, sum, s);

    const float inv = 1.0f / sum;
    #pragma unroll
    for (int i = 0; i < 8; i++) p[i * 32 + lane] = vals[i] * inv;
}

// ---------------------------------------------------------------------------
extern "C" void kernel_launch(void* const* d_in, const int* in_sizes, int n_in,
                              void* d_out, int out_size)
{
    const int*   sents  = (const int*)  d_in[0];
    const int*   datas  = (const int*)  d_in[1];
    const int*   slab   = (const int*)  d_in[2];
    const int*   dlab   = (const int*)  d_in[3];
    const float* emb    = (const float*)d_in[6];
    const float* Wi_f   = (const float*)d_in[7];
    const float* Wh_f   = (const float*)d_in[8];
    const float* b_f    = (const float*)d_in[9];
    const float* Wi_b   = (const float*)d_in[10];
    const float* Wh_b   = (const float*)d_in[11];
    const float* b_b    = (const float*)d_in[12];
    const float* WiD_f  = (const float*)d_in[13];
    const float* WhD_f  = (const float*)d_in[14];
    const float* bD_f   = (const float*)d_in[15];
    const float* WiD_b  = (const float*)d_in[16];
    const float* WhD_b  = (const float*)d_in[17];
    const float* bD_b   = (const float*)d_in[18];
    const float* W1     = (const float*)d_in[19];
    const float* W2     = (const float*)d_in[20];
    const float* v      = (const float*)d_in[21];
    float* out = (float*)d_out;

    k_xw<<<dim3(NROW / 128, 4, 4), 256>>>(
        sents, datas, emb,
        Wi_f, b_f, Wi_b, b_b, WiD_f, bD_f, WiD_b, bD_b);

    k_lstm<<<dim3(BB, 4), 256>>>(Wh_f, Wh_b, WhD_f, WhD_b);

    k_ent<<<dim3(BB, 2), 128>>>(slab, dlab);

    k_encdec<<<dim3(NROW / 128, 2), 256>>>(W1, W2);

    k_logits<<<dim3(BB, NEE / 32, NEE / 64), 256>>>(v, out);

    k_softmax<<<(BB * NEE) / 8, 256>>>(out);
}

// round 15
// speedup vs baseline: 1.1057x; 1.0003x over previous
#include <cuda_runtime.h>

// Problem constants
#define BB   32
#define TT   256
#define ESZ  128
#define HH   64
#define H4   256
#define H2   128
#define UU   64
#define NEE  256
#define NROW (BB*TT)   // 8192

// Scratch (device globals: no allocations allowed)
__device__ float g_xw [4][NROW][H4];        // input projections + bias, per (net,dir)
__device__ float g_rnn[2][BB][TT][H2];      // bilstm outputs (concat fwd/bwd)
__device__ float g_ent[2][BB][NEE][H2];     // 0: wordent, 1: dataent
__device__ float g_enc[BB][NEE][UU];        // dataent @ W1^T
__device__ float g_dec[BB][NEE][UU];        // wordent @ W2^T

__device__ __forceinline__ float tanha(float x) {
    float y; asm("tanh.approx.f32 %0, %1;" : "=f"(y) : "f"(x)); return y;
}
__device__ __forceinline__ float siga(float x) {   // sigmoid via MUFU.TANH
    return 0.5f + 0.5f * tanha(0.5f * x);
}
__device__ __forceinline__ unsigned f2tf32(float x) {
    unsigned r; asm("cvt.rna.tf32.f32 %0, %1;" : "=r"(r) : "f"(x)); return r;
}
__device__ __forceinline__ void mma_tf32(
    float& c0, float& c1, float& c2, float& c3,
    unsigned a0, unsigned a1, unsigned a2, unsigned a3,
    unsigned b0, unsigned b1)
{
    asm volatile(
        "mma.sync.aligned.m16n8k8.row.col.f32.tf32.tf32.f32 "
        "{%0,%1,%2,%3}, {%4,%5,%6,%7}, {%8,%9}, {%0,%1,%2,%3};"
        : "+f"(c0), "+f"(c1), "+f"(c2), "+f"(c3)
        : "r"(a0), "r"(a1), "r"(a2), "r"(a3), "r"(b0), "r"(b1));
}

// Shared tile layout: rows padded to 36 floats (36*4=144B = 9*16B: float4-aligned,
// and frag loads (4g+q addressing) are bank-conflict-free).
#define KPAD 36

// ---------------------------------------------------------------------------
// K1: fused embedding gather + input GEMM via tf32 tensor cores:
//   g_xw[combo][row][col] = b[col] + emb[tok[row]] . Wi[col]
// Block tile 128 rows x 64 cols, K=128 in 32-chunks. 8 warps, each 32x32.
// grid: (NROW/128, 4, 4): x=rowblk, y=colblk, z=combo.
// ---------------------------------------------------------------------------
__global__ __launch_bounds__(256) void k_xw(
    const int* __restrict__ sents, const int* __restrict__ datas,
    const float* __restrict__ emb,
    const float* __restrict__ Wi0, const float* __restrict__ b0,
    const float* __restrict__ Wi1, const float* __restrict__ b1,
    const float* __restrict__ Wi2, const float* __restrict__ b2,
    const float* __restrict__ Wi3, const float* __restrict__ b3)
{
    const int combo = blockIdx.z;
    const float* Wi = (combo == 0) ? Wi0 : (combo == 1) ? Wi1 : (combo == 2) ? Wi2 : Wi3;
    const float* bv = (combo == 0) ? b0  : (combo == 1) ? b1  : (combo == 2) ? b2  : b3;
    const int* toks = (combo < 2) ? sents : datas;

    __shared__ float As[128][KPAD];
    __shared__ float Bs[64][KPAD];
    __shared__ int   stok[128];

    const int tid = threadIdx.x;
    const int rowbase = blockIdx.x * 128;
    const int colbase = blockIdx.y * 64;

    if (tid < 128) stok[tid] = toks[rowbase + tid];

    const int warp = tid >> 5;
    const int lane = tid & 31;
    const int wr = (warp >> 1) * 32;       // warp row offset within tile
    const int wc = (warp & 1) * 32;        // warp col offset within tile
    const int rg = lane >> 2;              // 0..7
    const int q  = lane & 3;               // 0..3

    float c[2][4][4];                       // [mtile][ntile][frag]
    #pragma unroll
    for (int mt = 0; mt < 2; mt++)
        #pragma unroll
        for (int nt = 0; nt < 4; nt++)
            #pragma unroll
            for (int i = 0; i < 4; i++) c[mt][nt][i] = 0.0f;

    __syncthreads();

    for (int ks = 0; ks < 128; ks += 32) {
        // Load A: 128 rows x 32 k = 1024 float4 / 256 thr = 4 each (gathered emb)
        #pragma unroll
        for (int i = 0; i < 4; i++) {
            int lin = i * 256 + tid;
            int r  = lin >> 3;            // 0..127
            int kq = lin & 7;             // 0..7
            float4 av = *(const float4*)&emb[(size_t)stok[r] * ESZ + ks + kq * 4];
            *(float4*)&As[r][kq * 4] = av;
        }
        // Load B: 64 cols x 32 k = 512 float4 / 256 thr = 2 each
        #pragma unroll
        for (int i = 0; i < 2; i++) {
            int lin = i * 256 + tid;
            int r  = lin >> 3;            // 0..63
            int kq = lin & 7;
            float4 wv = *(const float4*)&Wi[(size_t)(colbase + r) * ESZ + ks + kq * 4];
            *(float4*)&Bs[r][kq * 4] = wv;
        }
        __syncthreads();

        #pragma unroll
        for (int kk = 0; kk < 32; kk += 8) {
            unsigned a[2][4], b[4][2];
            #pragma unroll
            for (int mt = 0; mt < 2; mt++) {
                int r = wr + 16 * mt + rg;
                a[mt][0] = f2tf32(As[r    ][kk + q]);
                a[mt][1] = f2tf32(As[r + 8][kk + q]);
                a[mt][2] = f2tf32(As[r    ][kk + q + 4]);
                a[mt][3] = f2tf32(As[r + 8][kk + q + 4]);
            }
            #pragma unroll
            for (int nt = 0; nt < 4; nt++) {
                int n = wc + 8 * nt + rg;
                b[nt][0] = f2tf32(Bs[n][kk + q]);
                b[nt][1] = f2tf32(Bs[n][kk + q + 4]);
            }
            #pragma unroll
            for (int mt = 0; mt < 2; mt++)
                #pragma unroll
                for (int nt = 0; nt < 4; nt++)
                    mma_tf32(c[mt][nt][0], c[mt][nt][1], c[mt][nt][2], c[mt][nt][3],
                             a[mt][0], a[mt][1], a[mt][2], a[mt][3],
                             b[nt][0], b[nt][1]);
        }
        __syncthreads();
    }

    // Epilogue: add bias, write g_xw
    #pragma unroll
    for (int mt = 0; mt < 2; mt++) {
        int r = rowbase + wr + 16 * mt + rg;
        #pragma unroll
        for (int nt = 0; nt < 4; nt++) {
            int col = colbase + wc + 8 * nt + 2 * q;
            float bx = bv[col], by = bv[col + 1];
            float2 v0 = make_float2(c[mt][nt][0] + bx, c[mt][nt][1] + by);
            float2 v1 = make_float2(c[mt][nt][2] + bx, c[mt][nt][3] + by);
            *(float2*)&g_xw[combo][r    ][col] = v0;
            *(float2*)&g_xw[combo][r + 8][col] = v1;
        }
    }
}

// ---------------------------------------------------------------------------
// K2: LSTM recurrence. One block per (b, combo). 256 threads: thread j owns
// z_j (Wh row j in registers, 4-way split accumulators).
// CHANGE vs best baseline: each thread applies its OWN gate's nonlinearity
// (sigma for i/f/o rows, tanh for g rows) BEFORE storing to z_s — in the
// fully-parallel 8-warp phase — so the serial 2-warp phase is just
// c/h state update + one tanh. Values are arithmetically identical.
// ---------------------------------------------------------------------------
__global__ __launch_bounds__(256) void k_lstm(
    const float* __restrict__ Wh0, const float* __restrict__ Wh1,
    const float* __restrict__ Wh2, const float* __restrict__ Wh3)
{
    const int b = blockIdx.x;
    const int combo = blockIdx.y;
    const int net = combo >> 1;
    const int dir = combo & 1;
    const float* Wh = (combo == 0) ? Wh0 : (combo == 1) ? Wh1 : (combo == 2) ? Wh2 : Wh3;

    const int j = threadIdx.x;
    const int sub = j >> 6;              // 0=i,1=f,2=g,3=o
    float wh[64];
    #pragma unroll
    for (int k4 = 0; k4 < 16; k4++) {
        float4 t4 = *(const float4*)&Wh[(size_t)j * HH + k4 * 4];
        wh[k4*4+0] = t4.x; wh[k4*4+1] = t4.y; wh[k4*4+2] = t4.z; wh[k4*4+3] = t4.w;
    }

    __shared__ __align__(16) float h_s[HH];
    __shared__ float z_s[H4];
    float cst = 0.0f;
    if (j < HH) h_s[j] = 0.0f;

    const float* xwp = &g_xw[combo][b * TT][0];
    const int tstep = dir ? -1 : 1;
    int t = dir ? (TT - 1) : 0;
    float xcur = xwp[t * H4 + j];
    __syncthreads();

    for (int ti = 0; ti < TT; ti++) {
        float xnext = (ti + 1 < TT) ? xwp[(t + tstep) * H4 + j] : 0.0f;

        float a0 = xcur, a1 = 0.0f, a2 = 0.0f, a3 = 0.0f;
        #pragma unroll
        for (int k4 = 0; k4 < 16; k4 += 4) {
            float4 h0 = ((const float4*)h_s)[k4 + 0];
            float4 h1 = ((const float4*)h_s)[k4 + 1];
            float4 h2 = ((const float4*)h_s)[k4 + 2];
            float4 h3 = ((const float4*)h_s)[k4 + 3];
            a0 = fmaf(wh[(k4+0)*4+0], h0.x, a0);
            a0 = fmaf(wh[(k4+0)*4+1], h0.y, a0);
            a0 = fmaf(wh[(k4+0)*4+2], h0.z, a0);
            a0 = fmaf(wh[(k4+0)*4+3], h0.w, a0);
            a1 = fmaf(wh[(k4+1)*4+0], h1.x, a1);
            a1 = fmaf(wh[(k4+1)*4+1], h1.y, a1);
            a1 = fmaf(wh[(k4+1)*4+2], h1.z, a1);
            a1 = fmaf(wh[(k4+1)*4+3], h1.w, a1);
            a2 = fmaf(wh[(k4+2)*4+0], h2.x, a2);
            a2 = fmaf(wh[(k4+2)*4+1], h2.y, a2);
            a2 = fmaf(wh[(k4+2)*4+2], h2.z, a2);
            a2 = fmaf(wh[(k4+2)*4+3], h2.w, a2);
            a3 = fmaf(wh[(k4+3)*4+0], h3.x, a3);
            a3 = fmaf(wh[(k4+3)*4+1], h3.y, a3);
            a3 = fmaf(wh[(k4+3)*4+2], h3.z, a3);
            a3 = fmaf(wh[(k4+3)*4+3], h3.w, a3);
        }
        const float z = (a0 + a1) + (a2 + a3);
        // Apply this row's gate nonlinearity here (parallel, 8 warps):
        // sigma for i/f/o (sub 0,1,3), tanh for g (sub 2). Same values as
        // computing them in the serial phase — just relocated.
        z_s[j] = (sub == 2) ? tanha(z) : siga(z);
        __syncthreads();
        if (j < HH) {
            float iv = z_s[j];
            float fv = z_s[j + HH];
            float gv = z_s[j + 2*HH];
            float ov = z_s[j + 3*HH];
            cst = fv * cst + iv * gv;
            float hv = ov * tanha(cst);
            h_s[j] = hv;
            g_rnn[net][b][t][dir * HH + j] = hv;
        }
        __syncthreads();
        xcur = xnext;
        t += tstep;
    }
}

// ---------------------------------------------------------------------------
// K3: entity extraction (segment means). One block per (b, which).
// ---------------------------------------------------------------------------
__global__ __launch_bounds__(128) void k_ent(
    const int* __restrict__ slab, const int* __restrict__ dlab)
{
    const int b = blockIdx.x;
    const int which = blockIdx.y;
    const int* lab = which ? dlab : slab;

    __shared__ int s_eid[TT];
    __shared__ int s_cnt[TT];
    __shared__ int s_closed;

    const int f = threadIdx.x;
    s_cnt[f] = 0; s_cnt[f + 128] = 0;
    __syncthreads();

    if (f == 0) {
        bool st = false; int ne = 0;
        for (int t = 0; t < TT; t++) {
            int l = lab[b * TT + t];
            if (l == 1)      { st = true; ne++; }
            else if (l == 0) { st = false; }
            if (st) { s_eid[t] = ne - 1; s_cnt[ne - 1]++; }
            else    { s_eid[t] = -1; }
        }
        s_closed = ne - (st ? 1 : 0);
    }
    __syncthreads();

    const int closed = s_closed;
    float* dst = &g_ent[which][b][0][0];
    for (int e = 0; e < NEE; e++) dst[e * H2 + f] = 0.0f;

    const float* src = &g_rnn[which][b][0][0];
    float acc = 0.0f; int cur = -1;
    for (int t = 0; t < TT; t++) {
        int e = s_eid[t];
        if (e != cur) {
            if (cur >= 0 && cur < closed) dst[cur * H2 + f] = acc / (float)s_cnt[cur];
            acc = 0.0f; cur = e;
        }
        if (e >= 0) acc += src[t * H2 + f];
    }
    if (cur >= 0 && cur < closed) dst[cur * H2 + f] = acc / (float)s_cnt[cur];
}

// ---------------------------------------------------------------------------
// K4: enc/dec projections via tf32 tensor cores.
// z=0: g_enc = dataent @ W1^T; z=1: g_dec = wordent @ W2^T
// Block tile 128 rows x 64 cols (full N), K=128 in 32-chunks. grid (64, 2).
// ---------------------------------------------------------------------------
__global__ __launch_bounds__(256) void k_encdec(
    const float* __restrict__ W1, const float* __restrict__ W2)
{
    const int z = blockIdx.y;
    const float* src = (z == 0) ? &g_ent[1][0][0][0] : &g_ent[0][0][0][0];
    const float* W   = (z == 0) ? W1 : W2;
    float* dst       = (z == 0) ? &g_enc[0][0][0] : &g_dec[0][0][0];

    __shared__ float As[128][KPAD];
    __shared__ float Bs[64][KPAD];

    const int tid = threadIdx.x;
    const int rowbase = blockIdx.x * 128;

    const int warp = tid >> 5;
    const int lane = tid & 31;
    const int wr = (warp >> 1) * 32;
    const int wc = (warp & 1) * 32;
    const int rg = lane >> 2;
    const int q  = lane & 3;

    float c[2][4][4];
    #pragma unroll
    for (int mt = 0; mt < 2; mt++)
        #pragma unroll
        for (int nt = 0; nt < 4; nt++)
            #pragma unroll
            for (int i = 0; i < 4; i++) c[mt][nt][i] = 0.0f;

    for (int ks = 0; ks < 128; ks += 32) {
        #pragma unroll
        for (int i = 0; i < 4; i++) {
            int lin = i * 256 + tid;
            int r  = lin >> 3;
            int kq = lin & 7;
            float4 av = *(const float4*)&src[(size_t)(rowbase + r) * H2 + ks + kq * 4];
            *(float4*)&As[r][kq * 4] = av;
        }
        #pragma unroll
        for (int i = 0; i < 2; i++) {
            int lin = i * 256 + tid;
            int r  = lin >> 3;
            int kq = lin & 7;
            float4 wv = *(const float4*)&W[(size_t)r * H2 + ks + kq * 4];
            *(float4*)&Bs[r][kq * 4] = wv;
        }
        __syncthreads();

        #pragma unroll
        for (int kk = 0; kk < 32; kk += 8) {
            unsigned a[2][4], b[4][2];
            #pragma unroll
            for (int mt = 0; mt < 2; mt++) {
                int r = wr + 16 * mt + rg;
                a[mt][0] = f2tf32(As[r    ][kk + q]);
                a[mt][1] = f2tf32(As[r + 8][kk + q]);
                a[mt][2] = f2tf32(As[r    ][kk + q + 4]);
                a[mt][3] = f2tf32(As[r + 8][kk + q + 4]);
            }
            #pragma unroll
            for (int nt = 0; nt < 4; nt++) {
                int n = wc + 8 * nt + rg;
                b[nt][0] = f2tf32(Bs[n][kk + q]);
                b[nt][1] = f2tf32(Bs[n][kk + q + 4]);
            }
            #pragma unroll
            for (int mt = 0; mt < 2; mt++)
                #pragma unroll
                for (int nt = 0; nt < 4; nt++)
                    mma_tf32(c[mt][nt][0], c[mt][nt][1], c[mt][nt][2], c[mt][nt][3],
                             a[mt][0], a[mt][1], a[mt][2], a[mt][3],
                             b[nt][0], b[nt][1]);
        }
        __syncthreads();
    }

    #pragma unroll
    for (int mt = 0; mt < 2; mt++) {
        int r = rowbase + wr + 16 * mt + rg;
        #pragma unroll
        for (int nt = 0; nt < 4; nt++) {
            int col = wc + 8 * nt + 2 * q;
            *(float2*)&dst[(size_t)r * UU + col] =
                make_float2(c[mt][nt][0], c[mt][nt][1]);
            *(float2*)&dst[(size_t)(r + 8) * UU + col] =
                make_float2(c[mt][nt][2], c[mt][nt][3]);
        }
    }
}

// ---------------------------------------------------------------------------
// K5: logits[b][w][d] = sum_u v[u] * tanh(enc[b][d][u] + dec[b][w][u])
// Block: (b, 32-w tile, 64-d tile). Hardware tanh.approx (MUFU.TANH).
// Kept SEPARATE from softmax: the fused variant measured +7 us (occupancy
// loss outweighs the saved logits round-trip).
// ---------------------------------------------------------------------------
__global__ __launch_bounds__(256) void k_logits(
    const float* __restrict__ v, float* __restrict__ out)
{
    const int b = blockIdx.x, wt = blockIdx.y, dt = blockIdx.z;

    __shared__ float enc_s[64][68];
    __shared__ float dec_s[32][68];
    __shared__ __align__(16) float v_s[64];

    const int tid = threadIdx.x;
    if (tid < 64) v_s[tid] = v[tid];

    #pragma unroll
    for (int i = 0; i < 4; i++) {
        int lin = i * 256 + tid;
        int d = lin >> 4, u4 = lin & 15;
        float4 val = *(const float4*)&g_enc[b][dt * 64 + d][u4 * 4];
        *(float4*)&enc_s[d][u4 * 4] = val;
    }
    #pragma unroll
    for (int i = 0; i < 2; i++) {
        int lin = i * 256 + tid;
        int w = lin >> 4, u4 = lin & 15;
        float4 val = *(const float4*)&g_dec[b][wt * 32 + w][u4 * 4];
        *(float4*)&dec_s[w][u4 * 4] = val;
    }
    __syncthreads();

    const int wloc = tid >> 3;     // 0..31
    const int dg   = tid & 7;      // 0..7
    float acc[8] = {0.f, 0.f, 0.f, 0.f, 0.f, 0.f, 0.f, 0.f};

    #pragma unroll
    for (int u4 = 0; u4 < 16; u4++) {
        float4 dv = *(const float4*)&dec_s[wloc][u4 * 4];
        float4 vv = *(const float4*)&v_s[u4 * 4];
        #pragma unroll
        for (int jj = 0; jj < 8; jj++) {
            float4 ev = *(const float4*)&enc_s[dg + 8 * jj][u4 * 4];
            acc[jj] = fmaf(vv.x, tanha(ev.x + dv.x), acc[jj]);
            acc[jj] = fmaf(vv.y, tanha(ev.y + dv.y), acc[jj]);
            acc[jj] = fmaf(vv.z, tanha(ev.z + dv.z), acc[jj]);
            acc[jj] = fmaf(vv.w, tanha(ev.w + dv.w), acc[jj]);
        }
    }

    const int w = wt * 32 + wloc;
    float* op = out + ((size_t)b * NEE + w) * NEE + dt * 64;
    #pragma unroll
    for (int jj = 0; jj < 8; jj++) op[dg + 8 * jj] = acc[jj];
}

// ---------------------------------------------------------------------------
// K6: in-place row softmax over last dim (256). One warp per row.
// ---------------------------------------------------------------------------
__global__ __launch_bounds__(256) void k_softmax(float* __restrict__ out)
{
    const int row  = blockIdx.x * 8 + (threadIdx.x >> 5);
    const int lane = threadIdx.x & 31;
    float* p = out + (size_t)row * NEE;

    float vals[8];
    float m = -1e30f;
    #pragma unroll
    for (int i = 0; i < 8; i++) {
        vals[i] = p[i * 32 + lane];
        m = fmaxf(m, vals[i]);
    }
    #pragma unroll
    for (int s = 16; s > 0; s >>= 1) m = fmaxf(m, __shfl_xor_sync(0xFFFFFFFFu, m, s));

    float sum = 0.0f;
    #pragma unroll
    for (int i = 0; i < 8; i++) {
        vals[i] = __expf(vals[i] - m);
        sum += vals[i];
    }
    #pragma unroll
    for (int s = 16; s > 0; s >>= 1) sum += __shfl_xor_sync(0xFFFFFFFFu, sum, s);

    const float inv = 1.0f / sum;
    #pragma unroll
    for (int i = 0; i < 8; i++) p[i * 32 + lane] = vals[i] * inv;
}

// ---------------------------------------------------------------------------
extern "C" void kernel_launch(void* const* d_in, const int* in_sizes, int n_in,
                              void* d_out, int out_size)
{
    const int*   sents  = (const int*)  d_in[0];
    const int*   datas  = (const int*)  d_in[1];
    const int*   slab   = (const int*)  d_in[2];
    const int*   dlab   = (const int*)  d_in[3];
    const float* emb    = (const float*)d_in[6];
    const float* Wi_f   = (const float*)d_in[7];
    const float* Wh_f   = (const float*)d_in[8];
    const float* b_f    = (const float*)d_in[9];
    const float* Wi_b   = (const float*)d_in[10];
    const float* Wh_b   = (const float*)d_in[11];
    const float* b_b    = (const float*)d_in[12];
    const float* WiD_f  = (const float*)d_in[13];
    const float* WhD_f  = (const float*)d_in[14];
    const float* bD_f   = (const float*)d_in[15];
    const float* WiD_b  = (const float*)d_in[16];
    const float* WhD_b  = (const float*)d_in[17];
    const float* bD_b   = (const float*)d_in[18];
    const float* W1     = (const float*)d_in[19];
    const float* W2     = (const float*)d_in[20];
    const float* v      = (const float*)d_in[21];
    float* out = (float*)d_out;

    k_xw<<<dim3(NROW / 128, 4, 4), 256>>>(
        sents, datas, emb,
        Wi_f, b_f, Wi_b, b_b, WiD_f, bD_f, WiD_b, bD_b);

    k_lstm<<<dim3(BB, 4), 256>>>(Wh_f, Wh_b, WhD_f, WhD_b);

    k_ent<<<dim3(BB, 2), 128>>>(slab, dlab);

    k_encdec<<<dim3(NROW / 128, 2), 256>>>(W1, W2);

    k_logits<<<dim3(BB, NEE / 32, NEE / 64), 256>>>(v, out);

    k_softmax<<<(BB * NEE) / 8, 256>>>(out);
}

// round 16
// speedup vs baseline: 1.2591x; 1.1387x over previous
#include <cuda_runtime.h>

// Problem constants
#define BB   32
#define TT   256
#define ESZ  128
#define HH   64
#define H4   256
#define H2   128
#define UU   64
#define NEE  256
#define NROW (BB*TT)   // 8192

// Scratch (device globals: no allocations allowed)
__device__ float g_xw [4][NROW][H4];        // input projections + bias, per (net,dir)
__device__ float g_rnn[2][BB][TT][H2];      // bilstm outputs (concat fwd/bwd)
__device__ float g_ent[2][BB][NEE][H2];     // 0: wordent, 1: dataent
__device__ float g_enc[BB][NEE][UU];        // dataent @ W1^T
__device__ float g_dec[BB][NEE][UU];        // wordent @ W2^T

__device__ __forceinline__ float tanha(float x) {
    float y; asm("tanh.approx.f32 %0, %1;" : "=f"(y) : "f"(x)); return y;
}
__device__ __forceinline__ float siga(float x) {   // sigmoid via MUFU.TANH
    return 0.5f + 0.5f * tanha(0.5f * x);
}
__device__ __forceinline__ unsigned f2tf32(float x) {
    unsigned r; asm("cvt.rna.tf32.f32 %0, %1;" : "=r"(r) : "f"(x)); return r;
}
__device__ __forceinline__ void mma_tf32(
    float& c0, float& c1, float& c2, float& c3,
    unsigned a0, unsigned a1, unsigned a2, unsigned a3,
    unsigned b0, unsigned b1)
{
    asm volatile(
        "mma.sync.aligned.m16n8k8.row.col.f32.tf32.tf32.f32 "
        "{%0,%1,%2,%3}, {%4,%5,%6,%7}, {%8,%9}, {%0,%1,%2,%3};"
        : "+f"(c0), "+f"(c1), "+f"(c2), "+f"(c3)
        : "r"(a0), "r"(a1), "r"(a2), "r"(a3), "r"(b0), "r"(b1));
}

// Shared tile layout: rows padded to 36 floats (36*4=144B = 9*16B: float4-aligned,
// and frag loads (4g+q addressing) are bank-conflict-free).
#define KPAD 36

// ---------------------------------------------------------------------------
// K1: fused embedding gather + input GEMM via tf32 tensor cores:
//   g_xw[combo][row][col] = b[col] + emb[tok[row]] . Wi[col]
// Block tile 128 rows x 64 cols, K=128 in 32-chunks. 8 warps, each 32x32.
// grid: (NROW/128, 4, 4): x=rowblk, y=colblk, z=combo.
// ---------------------------------------------------------------------------
__global__ __launch_bounds__(256) void k_xw(
    const int* __restrict__ sents, const int* __restrict__ datas,
    const float* __restrict__ emb,
    const float* __restrict__ Wi0, const float* __restrict__ b0,
    const float* __restrict__ Wi1, const float* __restrict__ b1,
    const float* __restrict__ Wi2, const float* __restrict__ b2,
    const float* __restrict__ Wi3, const float* __restrict__ b3)
{
    const int combo = blockIdx.z;
    const float* Wi = (combo == 0) ? Wi0 : (combo == 1) ? Wi1 : (combo == 2) ? Wi2 : Wi3;
    const float* bv = (combo == 0) ? b0  : (combo == 1) ? b1  : (combo == 2) ? b2  : b3;
    const int* toks = (combo < 2) ? sents : datas;

    __shared__ float As[128][KPAD];
    __shared__ float Bs[64][KPAD];
    __shared__ int   stok[128];

    const int tid = threadIdx.x;
    const int rowbase = blockIdx.x * 128;
    const int colbase = blockIdx.y * 64;

    if (tid < 128) stok[tid] = toks[rowbase + tid];

    const int warp = tid >> 5;
    const int lane = tid & 31;
    const int wr = (warp >> 1) * 32;       // warp row offset within tile
    const int wc = (warp & 1) * 32;        // warp col offset within tile
    const int rg = lane >> 2;              // 0..7
    const int q  = lane & 3;               // 0..3

    float c[2][4][4];                       // [mtile][ntile][frag]
    #pragma unroll
    for (int mt = 0; mt < 2; mt++)
        #pragma unroll
        for (int nt = 0; nt < 4; nt++)
            #pragma unroll
            for (int i = 0; i < 4; i++) c[mt][nt][i] = 0.0f;

    __syncthreads();

    for (int ks = 0; ks < 128; ks += 32) {
        // Load A: 128 rows x 32 k = 1024 float4 / 256 thr = 4 each (gathered emb)
        #pragma unroll
        for (int i = 0; i < 4; i++) {
            int lin = i * 256 + tid;
            int r  = lin >> 3;            // 0..127
            int kq = lin & 7;             // 0..7
            float4 av = *(const float4*)&emb[(size_t)stok[r] * ESZ + ks + kq * 4];
            *(float4*)&As[r][kq * 4] = av;
        }
        // Load B: 64 cols x 32 k = 512 float4 / 256 thr = 2 each
        #pragma unroll
        for (int i = 0; i < 2; i++) {
            int lin = i * 256 + tid;
            int r  = lin >> 3;            // 0..63
            int kq = lin & 7;
            float4 wv = *(const float4*)&Wi[(size_t)(colbase + r) * ESZ + ks + kq * 4];
            *(float4*)&Bs[r][kq * 4] = wv;
        }
        __syncthreads();

        #pragma unroll
        for (int kk = 0; kk < 32; kk += 8) {
            unsigned a[2][4], b[4][2];
            #pragma unroll
            for (int mt = 0; mt < 2; mt++) {
                int r = wr + 16 * mt + rg;
                a[mt][0] = f2tf32(As[r    ][kk + q]);
                a[mt][1] = f2tf32(As[r + 8][kk + q]);
                a[mt][2] = f2tf32(As[r    ][kk + q + 4]);
                a[mt][3] = f2tf32(As[r + 8][kk + q + 4]);
            }
            #pragma unroll
            for (int nt = 0; nt < 4; nt++) {
                int n = wc + 8 * nt + rg;
                b[nt][0] = f2tf32(Bs[n][kk + q]);
                b[nt][1] = f2tf32(Bs[n][kk + q + 4]);
            }
            #pragma unroll
            for (int mt = 0; mt < 2; mt++)
                #pragma unroll
                for (int nt = 0; nt < 4; nt++)
                    mma_tf32(c[mt][nt][0], c[mt][nt][1], c[mt][nt][2], c[mt][nt][3],
                             a[mt][0], a[mt][1], a[mt][2], a[mt][3],
                             b[nt][0], b[nt][1]);
        }
        __syncthreads();
    }

    // Epilogue: add bias, write g_xw
    #pragma unroll
    for (int mt = 0; mt < 2; mt++) {
        int r = rowbase + wr + 16 * mt + rg;
        #pragma unroll
        for (int nt = 0; nt < 4; nt++) {
            int col = colbase + wc + 8 * nt + 2 * q;
            float bx = bv[col], by = bv[col + 1];
            float2 v0 = make_float2(c[mt][nt][0] + bx, c[mt][nt][1] + by);
            float2 v1 = make_float2(c[mt][nt][2] + bx, c[mt][nt][3] + by);
            *(float2*)&g_xw[combo][r    ][col] = v0;
            *(float2*)&g_xw[combo][r + 8][col] = v1;
        }
    }
}

// ---------------------------------------------------------------------------
// K2: LSTM recurrence (best measured across 6 structural variants).
// One block per (b, combo). 256 threads: thread j owns z_j (Wh row j in
// registers, 4-way split accumulators). Gate nonlinearity applied per-thread
// in the parallel phase; threads 0..63 do the c/h state update.
// ---------------------------------------------------------------------------
__global__ __launch_bounds__(256) void k_lstm(
    const float* __restrict__ Wh0, const float* __restrict__ Wh1,
    const float* __restrict__ Wh2, const float* __restrict__ Wh3)
{
    const int b = blockIdx.x;
    const int combo = blockIdx.y;
    const int net = combo >> 1;
    const int dir = combo & 1;
    const float* Wh = (combo == 0) ? Wh0 : (combo == 1) ? Wh1 : (combo == 2) ? Wh2 : Wh3;

    const int j = threadIdx.x;
    const int sub = j >> 6;              // 0=i,1=f,2=g,3=o
    float wh[64];
    #pragma unroll
    for (int k4 = 0; k4 < 16; k4++) {
        float4 t4 = *(const float4*)&Wh[(size_t)j * HH + k4 * 4];
        wh[k4*4+0] = t4.x; wh[k4*4+1] = t4.y; wh[k4*4+2] = t4.z; wh[k4*4+3] = t4.w;
    }

    __shared__ __align__(16) float h_s[HH];
    __shared__ float z_s[H4];
    float cst = 0.0f;
    if (j < HH) h_s[j] = 0.0f;

    const float* xwp = &g_xw[combo][b * TT][0];
    const int tstep = dir ? -1 : 1;
    int t = dir ? (TT - 1) : 0;
    float xcur = xwp[t * H4 + j];
    __syncthreads();

    for (int ti = 0; ti < TT; ti++) {
        float xnext = (ti + 1 < TT) ? xwp[(t + tstep) * H4 + j] : 0.0f;

        float a0 = xcur, a1 = 0.0f, a2 = 0.0f, a3 = 0.0f;
        #pragma unroll
        for (int k4 = 0; k4 < 16; k4 += 4) {
            float4 h0 = ((const float4*)h_s)[k4 + 0];
            float4 h1 = ((const float4*)h_s)[k4 + 1];
            float4 h2 = ((const float4*)h_s)[k4 + 2];
            float4 h3 = ((const float4*)h_s)[k4 + 3];
            a0 = fmaf(wh[(k4+0)*4+0], h0.x, a0);
            a0 = fmaf(wh[(k4+0)*4+1], h0.y, a0);
            a0 = fmaf(wh[(k4+0)*4+2], h0.z, a0);
            a0 = fmaf(wh[(k4+0)*4+3], h0.w, a0);
            a1 = fmaf(wh[(k4+1)*4+0], h1.x, a1);
            a1 = fmaf(wh[(k4+1)*4+1], h1.y, a1);
            a1 = fmaf(wh[(k4+1)*4+2], h1.z, a1);
            a1 = fmaf(wh[(k4+1)*4+3], h1.w, a1);
            a2 = fmaf(wh[(k4+2)*4+0], h2.x, a2);
            a2 = fmaf(wh[(k4+2)*4+1], h2.y, a2);
            a2 = fmaf(wh[(k4+2)*4+2], h2.z, a2);
            a2 = fmaf(wh[(k4+2)*4+3], h2.w, a2);
            a3 = fmaf(wh[(k4+3)*4+0], h3.x, a3);
            a3 = fmaf(wh[(k4+3)*4+1], h3.y, a3);
            a3 = fmaf(wh[(k4+3)*4+2], h3.z, a3);
            a3 = fmaf(wh[(k4+3)*4+3], h3.w, a3);
        }
        const float z = (a0 + a1) + (a2 + a3);
        z_s[j] = (sub == 2) ? tanha(z) : siga(z);
        __syncthreads();
        if (j < HH) {
            float iv = z_s[j];
            float fv = z_s[j + HH];
            float gv = z_s[j + 2*HH];
            float ov = z_s[j + 3*HH];
            cst = fv * cst + iv * gv;
            float hv = ov * tanha(cst);
            h_s[j] = hv;
            g_rnn[net][b][t][dir * HH + j] = hv;
        }
        __syncthreads();
        xcur = xnext;
        t += tstep;
    }
}

// ---------------------------------------------------------------------------
// K3: entity extraction (segment means). One block per (b, which).
// CHANGES this round (memory behavior only; arithmetic order identical):
//  1. Labels staged to smem by all 128 threads (2 coalesced LDG each) before
//     thread 0's serial scan (LDS instead of 256 serial-ish LDGs).
//  2. Zero-fill restricted to entities [closed, NEE) — every e < closed is
//     written exactly once by the flush logic below.
//  3. src loads hoisted 4-ahead of the branchy segment logic (MLP=4).
// ---------------------------------------------------------------------------
__global__ __launch_bounds__(128) void k_ent(
    const int* __restrict__ slab, const int* __restrict__ dlab)
{
    const int b = blockIdx.x;
    const int which = blockIdx.y;
    const int* lab = which ? dlab : slab;

    __shared__ int s_lab[TT];
    __shared__ int s_eid[TT];
    __shared__ int s_cnt[TT];
    __shared__ int s_closed;

    const int f = threadIdx.x;
    s_lab[f]       = lab[b * TT + f];
    s_lab[f + 128] = lab[b * TT + f + 128];
    s_cnt[f] = 0; s_cnt[f + 128] = 0;
    __syncthreads();

    if (f == 0) {
        bool st = false; int ne = 0;
        for (int t = 0; t < TT; t++) {
            int l = s_lab[t];
            if (l == 1)      { st = true; ne++; }
            else if (l == 0) { st = false; }
            if (st) { s_eid[t] = ne - 1; s_cnt[ne - 1]++; }
            else    { s_eid[t] = -1; }
        }
        s_closed = ne - (st ? 1 : 0);
    }
    __syncthreads();

    const int closed = s_closed;
    float* dst = &g_ent[which][b][0][0];
    // Entities < closed each get exactly one mean write below; zero the rest.
    for (int e = closed; e < NEE; e++) dst[e * H2 + f] = 0.0f;

    const float* src = &g_rnn[which][b][0][0];
    float acc = 0.0f; int cur = -1;
    for (int t0 = 0; t0 < TT; t0 += 4) {
        // Hoist 4 loads ahead of the branchy segment logic (addresses are
        // state-independent, so these pipeline as MLP=4).
        float v0 = src[(t0 + 0) * H2 + f];
        float v1 = src[(t0 + 1) * H2 + f];
        float v2 = src[(t0 + 2) * H2 + f];
        float v3 = src[(t0 + 3) * H2 + f];
        #pragma unroll
        for (int k = 0; k < 4; k++) {
            const float v = (k == 0) ? v0 : (k == 1) ? v1 : (k == 2) ? v2 : v3;
            int e = s_eid[t0 + k];
            if (e != cur) {
                if (cur >= 0 && cur < closed) dst[cur * H2 + f] = acc / (float)s_cnt[cur];
                acc = 0.0f; cur = e;
            }
            if (e >= 0) acc += v;
        }
    }
    if (cur >= 0 && cur < closed) dst[cur * H2 + f] = acc / (float)s_cnt[cur];
}

// ---------------------------------------------------------------------------
// K4: enc/dec projections via tf32 tensor cores.
// z=0: g_enc = dataent @ W1^T; z=1: g_dec = wordent @ W2^T
// Block tile 128 rows x 64 cols (full N), K=128 in 32-chunks. grid (64, 2).
// ---------------------------------------------------------------------------
__global__ __launch_bounds__(256) void k_encdec(
    const float* __restrict__ W1, const float* __restrict__ W2)
{
    const int z = blockIdx.y;
    const float* src = (z == 0) ? &g_ent[1][0][0][0] : &g_ent[0][0][0][0];
    const float* W   = (z == 0) ? W1 : W2;
    float* dst       = (z == 0) ? &g_enc[0][0][0] : &g_dec[0][0][0];

    __shared__ float As[128][KPAD];
    __shared__ float Bs[64][KPAD];

    const int tid = threadIdx.x;
    const int rowbase = blockIdx.x * 128;

    const int warp = tid >> 5;
    const int lane = tid & 31;
    const int wr = (warp >> 1) * 32;
    const int wc = (warp & 1) * 32;
    const int rg = lane >> 2;
    const int q  = lane & 3;

    float c[2][4][4];
    #pragma unroll
    for (int mt = 0; mt < 2; mt++)
        #pragma unroll
        for (int nt = 0; nt < 4; nt++)
            #pragma unroll
            for (int i = 0; i < 4; i++) c[mt][nt][i] = 0.0f;

    for (int ks = 0; ks < 128; ks += 32) {
        #pragma unroll
        for (int i = 0; i < 4; i++) {
            int lin = i * 256 + tid;
            int r  = lin >> 3;
            int kq = lin & 7;
            float4 av = *(const float4*)&src[(size_t)(rowbase + r) * H2 + ks + kq * 4];
            *(float4*)&As[r][kq * 4] = av;
        }
        #pragma unroll
        for (int i = 0; i < 2; i++) {
            int lin = i * 256 + tid;
            int r  = lin >> 3;
            int kq = lin & 7;
            float4 wv = *(const float4*)&W[(size_t)r * H2 + ks + kq * 4];
            *(float4*)&Bs[r][kq * 4] = wv;
        }
        __syncthreads();

        #pragma unroll
        for (int kk = 0; kk < 32; kk += 8) {
            unsigned a[2][4], b[4][2];
            #pragma unroll
            for (int mt = 0; mt < 2; mt++) {
                int r = wr + 16 * mt + rg;
                a[mt][0] = f2tf32(As[r    ][kk + q]);
                a[mt][1] = f2tf32(As[r + 8][kk + q]);
                a[mt][2] = f2tf32(As[r    ][kk + q + 4]);
                a[mt][3] = f2tf32(As[r + 8][kk + q + 4]);
            }
            #pragma unroll
            for (int nt = 0; nt < 4; nt++) {
                int n = wc + 8 * nt + rg;
                b[nt][0] = f2tf32(Bs[n][kk + q]);
                b[nt][1] = f2tf32(Bs[n][kk + q + 4]);
            }
            #pragma unroll
            for (int mt = 0; mt < 2; mt++)
                #pragma unroll
                for (int nt = 0; nt < 4; nt++)
                    mma_tf32(c[mt][nt][0], c[mt][nt][1], c[mt][nt][2], c[mt][nt][3],
                             a[mt][0], a[mt][1], a[mt][2], a[mt][3],
                             b[nt][0], b[nt][1]);
        }
        __syncthreads();
    }

    #pragma unroll
    for (int mt = 0; mt < 2; mt++) {
        int r = rowbase + wr + 16 * mt + rg;
        #pragma unroll
        for (int nt = 0; nt < 4; nt++) {
            int col = wc + 8 * nt + 2 * q;
            *(float2*)&dst[(size_t)r * UU + col] =
                make_float2(c[mt][nt][0], c[mt][nt][1]);
            *(float2*)&dst[(size_t)(r + 8) * UU + col] =
                make_float2(c[mt][nt][2], c[mt][nt][3]);
        }
    }
}

// ---------------------------------------------------------------------------
// K5: logits[b][w][d] = sum_u v[u] * tanh(enc[b][d][u] + dec[b][w][u])
// Block: (b, 32-w tile, 64-d tile). Hardware tanh.approx (MUFU.TANH).
// Kept SEPARATE from softmax: the fused variant measured +7 us (occupancy
// loss outweighs the saved logits round-trip).
// ---------------------------------------------------------------------------
__global__ __launch_bounds__(256) void k_logits(
    const float* __restrict__ v, float* __restrict__ out)
{
    const int b = blockIdx.x, wt = blockIdx.y, dt = blockIdx.z;

    __shared__ float enc_s[64][68];
    __shared__ float dec_s[32][68];
    __shared__ __align__(16) float v_s[64];

    const int tid = threadIdx.x;
    if (tid < 64) v_s[tid] = v[tid];

    #pragma unroll
    for (int i = 0; i < 4; i++) {
        int lin = i * 256 + tid;
        int d = lin >> 4, u4 = lin & 15;
        float4 val = *(const float4*)&g_enc[b][dt * 64 + d][u4 * 4];
        *(float4*)&enc_s[d][u4 * 4] = val;
    }
    #pragma unroll
    for (int i = 0; i < 2; i++) {
        int lin = i * 256 + tid;
        int w = lin >> 4, u4 = lin & 15;
        float4 val = *(const float4*)&g_dec[b][wt * 32 + w][u4 * 4];
        *(float4*)&dec_s[w][u4 * 4] = val;
    }
    __syncthreads();

    const int wloc = tid >> 3;     // 0..31
    const int dg   = tid & 7;      // 0..7
    float acc[8] = {0.f, 0.f, 0.f, 0.f, 0.f, 0.f, 0.f, 0.f};

    #pragma unroll
    for (int u4 = 0; u4 < 16; u4++) {
        float4 dv = *(const float4*)&dec_s[wloc][u4 * 4];
        float4 vv = *(const float4*)&v_s[u4 * 4];
        #pragma unroll
        for (int jj = 0; jj < 8; jj++) {
            float4 ev = *(const float4*)&enc_s[dg + 8 * jj][u4 * 4];
            acc[jj] = fmaf(vv.x, tanha(ev.x + dv.x), acc[jj]);
            acc[jj] = fmaf(vv.y, tanha(ev.y + dv.y), acc[jj]);
            acc[jj] = fmaf(vv.z, tanha(ev.z + dv.z), acc[jj]);
            acc[jj] = fmaf(vv.w, tanha(ev.w + dv.w), acc[jj]);
        }
    }

    const int w = wt * 32 + wloc;
    float* op = out + ((size_t)b * NEE + w) * NEE + dt * 64;
    #pragma unroll
    for (int jj = 0; jj < 8; jj++) op[dg + 8 * jj] = acc[jj];
}

// ---------------------------------------------------------------------------
// K6: in-place row softmax over last dim (256). One warp per row.
// ---------------------------------------------------------------------------
__global__ __launch_bounds__(256) void k_softmax(float* __restrict__ out)
{
    const int row  = blockIdx.x * 8 + (threadIdx.x >> 5);
    const int lane = threadIdx.x & 31;
    float* p = out + (size_t)row * NEE;

    float vals[8];
    float m = -1e30f;
    #pragma unroll
    for (int i = 0; i < 8; i++) {
        vals[i] = p[i * 32 + lane];
        m = fmaxf(m, vals[i]);
    }
    #pragma unroll
    for (int s = 16; s > 0; s >>= 1) m = fmaxf(m, __shfl_xor_sync(0xFFFFFFFFu, m, s));

    float sum = 0.0f;
    #pragma unroll
    for (int i = 0; i < 8; i++) {
        vals[i] = __expf(vals[i] - m);
        sum += vals[i];
    }
    #pragma unroll
    for (int s = 16; s > 0; s >>= 1) sum += __shfl_xor_sync(0xFFFFFFFFu, sum, s);

    const float inv = 1.0f / sum;
    #pragma unroll
    for (int i = 0; i < 8; i++) p[i * 32 + lane] = vals[i] * inv;
}

// ---------------------------------------------------------------------------
extern "C" void kernel_launch(void* const* d_in, const int* in_sizes, int n_in,
                              void* d_out, int out_size)
{
    const int*   sents  = (const int*)  d_in[0];
    const int*   datas  = (const int*)  d_in[1];
    const int*   slab   = (const int*)  d_in[2];
    const int*   dlab   = (const int*)  d_in[3];
    const float* emb    = (const float*)d_in[6];
    const float* Wi_f   = (const float*)d_in[7];
    const float* Wh_f   = (const float*)d_in[8];
    const float* b_f    = (const float*)d_in[9];
    const float* Wi_b   = (const float*)d_in[10];
    const float* Wh_b   = (const float*)d_in[11];
    const float* b_b    = (const float*)d_in[12];
    const float* WiD_f  = (const float*)d_in[13];
    const float* WhD_f  = (const float*)d_in[14];
    const float* bD_f   = (const float*)d_in[15];
    const float* WiD_b  = (const float*)d_in[16];
    const float* WhD_b  = (const float*)d_in[17];
    const float* bD_b   = (const float*)d_in[18];
    const float* W1     = (const float*)d_in[19];
    const float* W2     = (const float*)d_in[20];
    const float* v      = (const float*)d_in[21];
    float* out = (float*)d_out;

    k_xw<<<dim3(NROW / 128, 4, 4), 256>>>(
        sents, datas, emb,
        Wi_f, b_f, Wi_b, b_b, WiD_f, bD_f, WiD_b, bD_b);

    k_lstm<<<dim3(BB, 4), 256>>>(Wh_f, Wh_b, WhD_f, WhD_b);

    k_ent<<<dim3(BB, 2), 128>>>(slab, dlab);

    k_encdec<<<dim3(NROW / 128, 2), 256>>>(W1, W2);

    k_logits<<<dim3(BB, NEE / 32, NEE / 64), 256>>>(v, out);

    k_softmax<<<(BB * NEE) / 8, 256>>>(out);
}

// round 17
// speedup vs baseline: 1.3202x; 1.0485x over previous
#include <cuda_runtime.h>

// Problem constants
#define BB   32
#define TT   256
#define ESZ  128
#define HH   64
#define H4   256
#define H2   128
#define UU   64
#define NEE  256
#define NROW (BB*TT)   // 8192

// Scratch (device globals: no allocations allowed)
__device__ float g_xw [4][NROW][H4];        // input projections + bias, per (net,dir)
__device__ float g_rnn[2][BB][TT][H2];      // bilstm outputs (concat fwd/bwd)
__device__ float g_ent[2][BB][NEE][H2];     // 0: wordent, 1: dataent
__device__ float g_enc[BB][NEE][UU];        // dataent @ W1^T
__device__ float g_dec[BB][NEE][UU];        // wordent @ W2^T

__device__ __forceinline__ float tanha(float x) {
    float y; asm("tanh.approx.f32 %0, %1;" : "=f"(y) : "f"(x)); return y;
}
__device__ __forceinline__ float siga(float x) {   // sigmoid via MUFU.TANH
    return 0.5f + 0.5f * tanha(0.5f * x);
}
__device__ __forceinline__ unsigned f2tf32(float x) {
    unsigned r; asm("cvt.rna.tf32.f32 %0, %1;" : "=r"(r) : "f"(x)); return r;
}
__device__ __forceinline__ void mma_tf32(
    float& c0, float& c1, float& c2, float& c3,
    unsigned a0, unsigned a1, unsigned a2, unsigned a3,
    unsigned b0, unsigned b1)
{
    asm volatile(
        "mma.sync.aligned.m16n8k8.row.col.f32.tf32.tf32.f32 "
        "{%0,%1,%2,%3}, {%4,%5,%6,%7}, {%8,%9}, {%0,%1,%2,%3};"
        : "+f"(c0), "+f"(c1), "+f"(c2), "+f"(c3)
        : "r"(a0), "r"(a1), "r"(a2), "r"(a3), "r"(b0), "r"(b1));
}

// Shared tile layout: rows padded to 36 floats (36*4=144B = 9*16B: float4-aligned,
// and frag loads (4g+q addressing) are bank-conflict-free).
#define KPAD 36

// ---------------------------------------------------------------------------
// K1: fused embedding gather + input GEMM via tf32 tensor cores:
//   g_xw[combo][row][col] = b[col] + emb[tok[row]] . Wi[col]
// Block tile 128 rows x 64 cols, K=128 in 32-chunks. 8 warps, each 32x32.
// Software-pipelined: chunk i+1's LDGs issued into registers before the mma
// loop on chunk i (hides L2/DRAM latency; arithmetic identical).
// grid: (NROW/128, 4, 4): x=rowblk, y=colblk, z=combo.
// ---------------------------------------------------------------------------
__global__ __launch_bounds__(256) void k_xw(
    const int* __restrict__ sents, const int* __restrict__ datas,
    const float* __restrict__ emb,
    const float* __restrict__ Wi0, const float* __restrict__ b0,
    const float* __restrict__ Wi1, const float* __restrict__ b1,
    const float* __restrict__ Wi2, const float* __restrict__ b2,
    const float* __restrict__ Wi3, const float* __restrict__ b3)
{
    const int combo = blockIdx.z;
    const float* Wi = (combo == 0) ? Wi0 : (combo == 1) ? Wi1 : (combo == 2) ? Wi2 : Wi3;
    const float* bv = (combo == 0) ? b0  : (combo == 1) ? b1  : (combo == 2) ? b2  : b3;
    const int* toks = (combo < 2) ? sents : datas;

    __shared__ float As[128][KPAD];
    __shared__ float Bs[64][KPAD];
    __shared__ int   stok[128];

    const int tid = threadIdx.x;
    const int rowbase = blockIdx.x * 128;
    const int colbase = blockIdx.y * 64;

    if (tid < 128) stok[tid] = toks[rowbase + tid];

    const int warp = tid >> 5;
    const int lane = tid & 31;
    const int wr = (warp >> 1) * 32;       // warp row offset within tile
    const int wc = (warp & 1) * 32;        // warp col offset within tile
    const int rg = lane >> 2;              // 0..7
    const int q  = lane & 3;               // 0..3

    // Per-thread staging indices for tile loads
    const int ar = tid >> 1;               // A row this thread loads (2 kq each)
    const int br = tid >> 2;               // B row (4 threads * ... ) -- see below

    float c[2][4][4];                       // [mtile][ntile][frag]
    #pragma unroll
    for (int mt = 0; mt < 2; mt++)
        #pragma unroll
        for (int nt = 0; nt < 4; nt++)
            #pragma unroll
            for (int i = 0; i < 4; i++) c[mt][nt][i] = 0.0f;

    __syncthreads();   // stok visible

    float4 avr[4];   // A stage: 4 float4 per thread (1024 total)
    float4 wvr[2];   // B stage: 2 float4 per thread (512 total)

    // Preload chunk 0
    #pragma unroll
    for (int i = 0; i < 4; i++) {
        int lin = i * 256 + tid;
        int r  = lin >> 3;
        int kq = lin & 7;
        avr[i] = *(const float4*)&emb[(size_t)stok[r] * ESZ + 0 + kq * 4];
    }
    #pragma unroll
    for (int i = 0; i < 2; i++) {
        int lin = i * 256 + tid;
        int r  = lin >> 3;
        int kq = lin & 7;
        wvr[i] = *(const float4*)&Wi[(size_t)(colbase + r) * ESZ + 0 + kq * 4];
    }

    for (int cchunk = 0; cchunk < 4; cchunk++) {
        // Stage registers -> smem
        #pragma unroll
        for (int i = 0; i < 4; i++) {
            int lin = i * 256 + tid;
            int r  = lin >> 3;
            int kq = lin & 7;
            *(float4*)&As[r][kq * 4] = avr[i];
        }
        #pragma unroll
        for (int i = 0; i < 2; i++) {
            int lin = i * 256 + tid;
            int r  = lin >> 3;
            int kq = lin & 7;
            *(float4*)&Bs[r][kq * 4] = wvr[i];
        }
        __syncthreads();

        // Prefetch next chunk (LDG latency overlapped with the mma loop)
        if (cchunk + 1 < 4) {
            const int ks = (cchunk + 1) * 32;
            #pragma unroll
            for (int i = 0; i < 4; i++) {
                int lin = i * 256 + tid;
                int r  = lin >> 3;
                int kq = lin & 7;
                avr[i] = *(const float4*)&emb[(size_t)stok[r] * ESZ + ks + kq * 4];
            }
            #pragma unroll
            for (int i = 0; i < 2; i++) {
                int lin = i * 256 + tid;
                int r  = lin >> 3;
                int kq = lin & 7;
                wvr[i] = *(const float4*)&Wi[(size_t)(colbase + r) * ESZ + ks + kq * 4];
            }
        }

        #pragma unroll
        for (int kk = 0; kk < 32; kk += 8) {
            unsigned a[2][4], b[4][2];
            #pragma unroll
            for (int mt = 0; mt < 2; mt++) {
                int r = wr + 16 * mt + rg;
                a[mt][0] = f2tf32(As[r    ][kk + q]);
                a[mt][1] = f2tf32(As[r + 8][kk + q]);
                a[mt][2] = f2tf32(As[r    ][kk + q + 4]);
                a[mt][3] = f2tf32(As[r + 8][kk + q + 4]);
            }
            #pragma unroll
            for (int nt = 0; nt < 4; nt++) {
                int n = wc + 8 * nt + rg;
                b[nt][0] = f2tf32(Bs[n][kk + q]);
                b[nt][1] = f2tf32(Bs[n][kk + q + 4]);
            }
            #pragma unroll
            for (int mt = 0; mt < 2; mt++)
                #pragma unroll
                for (int nt = 0; nt < 4; nt++)
                    mma_tf32(c[mt][nt][0], c[mt][nt][1], c[mt][nt][2], c[mt][nt][3],
                             a[mt][0], a[mt][1], a[mt][2], a[mt][3],
                             b[nt][0], b[nt][1]);
        }
        __syncthreads();
    }

    // Epilogue: add bias, write g_xw
    #pragma unroll
    for (int mt = 0; mt < 2; mt++) {
        int r = rowbase + wr + 16 * mt + rg;
        #pragma unroll
        for (int nt = 0; nt < 4; nt++) {
            int col = colbase + wc + 8 * nt + 2 * q;
            float bx = bv[col], by = bv[col + 1];
            float2 v0 = make_float2(c[mt][nt][0] + bx, c[mt][nt][1] + by);
            float2 v1 = make_float2(c[mt][nt][2] + bx, c[mt][nt][3] + by);
            *(float2*)&g_xw[combo][r    ][col] = v0;
            *(float2*)&g_xw[combo][r + 8][col] = v1;
        }
    }
}

// ---------------------------------------------------------------------------
// K2: LSTM recurrence (best measured across 6 structural variants — frozen).
// One block per (b, combo). 256 threads: thread j owns z_j (Wh row j in
// registers, 4-way split accumulators). Gate nonlinearity applied per-thread
// in the parallel phase; threads 0..63 do the c/h state update.
// ---------------------------------------------------------------------------
__global__ __launch_bounds__(256) void k_lstm(
    const float* __restrict__ Wh0, const float* __restrict__ Wh1,
    const float* __restrict__ Wh2, const float* __restrict__ Wh3)
{
    const int b = blockIdx.x;
    const int combo = blockIdx.y;
    const int net = combo >> 1;
    const int dir = combo & 1;
    const float* Wh = (combo == 0) ? Wh0 : (combo == 1) ? Wh1 : (combo == 2) ? Wh2 : Wh3;

    const int j = threadIdx.x;
    const int sub = j >> 6;              // 0=i,1=f,2=g,3=o
    float wh[64];
    #pragma unroll
    for (int k4 = 0; k4 < 16; k4++) {
        float4 t4 = *(const float4*)&Wh[(size_t)j * HH + k4 * 4];
        wh[k4*4+0] = t4.x; wh[k4*4+1] = t4.y; wh[k4*4+2] = t4.z; wh[k4*4+3] = t4.w;
    }

    __shared__ __align__(16) float h_s[HH];
    __shared__ float z_s[H4];
    float cst = 0.0f;
    if (j < HH) h_s[j] = 0.0f;

    const float* xwp = &g_xw[combo][b * TT][0];
    const int tstep = dir ? -1 : 1;
    int t = dir ? (TT - 1) : 0;
    float xcur = xwp[t * H4 + j];
    __syncthreads();

    for (int ti = 0; ti < TT; ti++) {
        float xnext = (ti + 1 < TT) ? xwp[(t + tstep) * H4 + j] : 0.0f;

        float a0 = xcur, a1 = 0.0f, a2 = 0.0f, a3 = 0.0f;
        #pragma unroll
        for (int k4 = 0; k4 < 16; k4 += 4) {
            float4 h0 = ((const float4*)h_s)[k4 + 0];
            float4 h1 = ((const float4*)h_s)[k4 + 1];
            float4 h2 = ((const float4*)h_s)[k4 + 2];
            float4 h3 = ((const float4*)h_s)[k4 + 3];
            a0 = fmaf(wh[(k4+0)*4+0], h0.x, a0);
            a0 = fmaf(wh[(k4+0)*4+1], h0.y, a0);
            a0 = fmaf(wh[(k4+0)*4+2], h0.z, a0);
            a0 = fmaf(wh[(k4+0)*4+3], h0.w, a0);
            a1 = fmaf(wh[(k4+1)*4+0], h1.x, a1);
            a1 = fmaf(wh[(k4+1)*4+1], h1.y, a1);
            a1 = fmaf(wh[(k4+1)*4+2], h1.z, a1);
            a1 = fmaf(wh[(k4+1)*4+3], h1.w, a1);
            a2 = fmaf(wh[(k4+2)*4+0], h2.x, a2);
            a2 = fmaf(wh[(k4+2)*4+1], h2.y, a2);
            a2 = fmaf(wh[(k4+2)*4+2], h2.z, a2);
            a2 = fmaf(wh[(k4+2)*4+3], h2.w, a2);
            a3 = fmaf(wh[(k4+3)*4+0], h3.x, a3);
            a3 = fmaf(wh[(k4+3)*4+1], h3.y, a3);
            a3 = fmaf(wh[(k4+3)*4+2], h3.z, a3);
            a3 = fmaf(wh[(k4+3)*4+3], h3.w, a3);
        }
        const float z = (a0 + a1) + (a2 + a3);
        z_s[j] = (sub == 2) ? tanha(z) : siga(z);
        __syncthreads();
        if (j < HH) {
            float iv = z_s[j];
            float fv = z_s[j + HH];
            float gv = z_s[j + 2*HH];
            float ov = z_s[j + 3*HH];
            cst = fv * cst + iv * gv;
            float hv = ov * tanha(cst);
            h_s[j] = hv;
            g_rnn[net][b][t][dir * HH + j] = hv;
        }
        __syncthreads();
        xcur = xnext;
        t += tstep;
    }
}

// ---------------------------------------------------------------------------
// K3: entity extraction (segment means). One block per (b, which).
// smem-staged labels, zero-fill only [closed, NEE), src loads hoisted MLP=4.
// ---------------------------------------------------------------------------
__global__ __launch_bounds__(128) void k_ent(
    const int* __restrict__ slab, const int* __restrict__ dlab)
{
    const int b = blockIdx.x;
    const int which = blockIdx.y;
    const int* lab = which ? dlab : slab;

    __shared__ int s_lab[TT];
    __shared__ int s_eid[TT];
    __shared__ int s_cnt[TT];
    __shared__ int s_closed;

    const int f = threadIdx.x;
    s_lab[f]       = lab[b * TT + f];
    s_lab[f + 128] = lab[b * TT + f + 128];
    s_cnt[f] = 0; s_cnt[f + 128] = 0;
    __syncthreads();

    if (f == 0) {
        bool st = false; int ne = 0;
        for (int t = 0; t < TT; t++) {
            int l = s_lab[t];
            if (l == 1)      { st = true; ne++; }
            else if (l == 0) { st = false; }
            if (st) { s_eid[t] = ne - 1; s_cnt[ne - 1]++; }
            else    { s_eid[t] = -1; }
        }
        s_closed = ne - (st ? 1 : 0);
    }
    __syncthreads();

    const int closed = s_closed;
    float* dst = &g_ent[which][b][0][0];
    for (int e = closed; e < NEE; e++) dst[e * H2 + f] = 0.0f;

    const float* src = &g_rnn[which][b][0][0];
    float acc = 0.0f; int cur = -1;
    for (int t0 = 0; t0 < TT; t0 += 4) {
        float v0 = src[(t0 + 0) * H2 + f];
        float v1 = src[(t0 + 1) * H2 + f];
        float v2 = src[(t0 + 2) * H2 + f];
        float v3 = src[(t0 + 3) * H2 + f];
        #pragma unroll
        for (int k = 0; k < 4; k++) {
            const float v = (k == 0) ? v0 : (k == 1) ? v1 : (k == 2) ? v2 : v3;
            int e = s_eid[t0 + k];
            if (e != cur) {
                if (cur >= 0 && cur < closed) dst[cur * H2 + f] = acc / (float)s_cnt[cur];
                acc = 0.0f; cur = e;
            }
            if (e >= 0) acc += v;
        }
    }
    if (cur >= 0 && cur < closed) dst[cur * H2 + f] = acc / (float)s_cnt[cur];
}

// ---------------------------------------------------------------------------
// K4: enc/dec projections via tf32 tensor cores, software-pipelined:
// chunk i+1's LDGs issued into registers before the mma loop on chunk i.
// z=0: g_enc = dataent @ W1^T; z=1: g_dec = wordent @ W2^T
// Block tile 128 rows x 64 cols (full N), K=128 in 32-chunks. grid (64, 2).
// ---------------------------------------------------------------------------
__global__ __launch_bounds__(256) void k_encdec(
    const float* __restrict__ W1, const float* __restrict__ W2)
{
    const int z = blockIdx.y;
    const float* src = (z == 0) ? &g_ent[1][0][0][0] : &g_ent[0][0][0][0];
    const float* W   = (z == 0) ? W1 : W2;
    float* dst       = (z == 0) ? &g_enc[0][0][0] : &g_dec[0][0][0];

    __shared__ float As[128][KPAD];
    __shared__ float Bs[64][KPAD];

    const int tid = threadIdx.x;
    const int rowbase = blockIdx.x * 128;

    const int warp = tid >> 5;
    const int lane = tid & 31;
    const int wr = (warp >> 1) * 32;
    const int wc = (warp & 1) * 32;
    const int rg = lane >> 2;
    const int q  = lane & 3;

    float c[2][4][4];
    #pragma unroll
    for (int mt = 0; mt < 2; mt++)
        #pragma unroll
        for (int nt = 0; nt < 4; nt++)
            #pragma unroll
            for (int i = 0; i < 4; i++) c[mt][nt][i] = 0.0f;

    float4 avr[4];
    float4 wvr[2];

    // Preload chunk 0
    #pragma unroll
    for (int i = 0; i < 4; i++) {
        int lin = i * 256 + tid;
        int r  = lin >> 3;
        int kq = lin & 7;
        avr[i] = *(const float4*)&src[(size_t)(rowbase + r) * H2 + 0 + kq * 4];
    }
    #pragma unroll
    for (int i = 0; i < 2; i++) {
        int lin = i * 256 + tid;
        int r  = lin >> 3;
        int kq = lin & 7;
        wvr[i] = *(const float4*)&W[(size_t)r * H2 + 0 + kq * 4];
    }

    for (int cchunk = 0; cchunk < 4; cchunk++) {
        #pragma unroll
        for (int i = 0; i < 4; i++) {
            int lin = i * 256 + tid;
            int r  = lin >> 3;
            int kq = lin & 7;
            *(float4*)&As[r][kq * 4] = avr[i];
        }
        #pragma unroll
        for (int i = 0; i < 2; i++) {
            int lin = i * 256 + tid;
            int r  = lin >> 3;
            int kq = lin & 7;
            *(float4*)&Bs[r][kq * 4] = wvr[i];
        }
        __syncthreads();

        if (cchunk + 1 < 4) {
            const int ks = (cchunk + 1) * 32;
            #pragma unroll
            for (int i = 0; i < 4; i++) {
                int lin = i * 256 + tid;
                int r  = lin >> 3;
                int kq = lin & 7;
                avr[i] = *(const float4*)&src[(size_t)(rowbase + r) * H2 + ks + kq * 4];
            }
            #pragma unroll
            for (int i = 0; i < 2; i++) {
                int lin = i * 256 + tid;
                int r  = lin >> 3;
                int kq = lin & 7;
                wvr[i] = *(const float4*)&W[(size_t)r * H2 + ks + kq * 4];
            }
        }

        #pragma unroll
        for (int kk = 0; kk < 32; kk += 8) {
            unsigned a[2][4], b[4][2];
            #pragma unroll
            for (int mt = 0; mt < 2; mt++) {
                int r = wr + 16 * mt + rg;
                a[mt][0] = f2tf32(As[r    ][kk + q]);
                a[mt][1] = f2tf32(As[r + 8][kk + q]);
                a[mt][2] = f2tf32(As[r    ][kk + q + 4]);
                a[mt][3] = f2tf32(As[r + 8][kk + q + 4]);
            }
            #pragma unroll
            for (int nt = 0; nt < 4; nt++) {
                int n = wc + 8 * nt + rg;
                b[nt][0] = f2tf32(Bs[n][kk + q]);
                b[nt][1] = f2tf32(Bs[n][kk + q + 4]);
            }
            #pragma unroll
            for (int mt = 0; mt < 2; mt++)
                #pragma unroll
                for (int nt = 0; nt < 4; nt++)
                    mma_tf32(c[mt][nt][0], c[mt][nt][1], c[mt][nt][2], c[mt][nt][3],
                             a[mt][0], a[mt][1], a[mt][2], a[mt][3],
                             b[nt][0], b[nt][1]);
        }
        __syncthreads();
    }

    #pragma unroll
    for (int mt = 0; mt < 2; mt++) {
        int r = rowbase + wr + 16 * mt + rg;
        #pragma unroll
        for (int nt = 0; nt < 4; nt++) {
            int col = wc + 8 * nt + 2 * q;
            *(float2*)&dst[(size_t)r * UU + col] =
                make_float2(c[mt][nt][0], c[mt][nt][1]);
            *(float2*)&dst[(size_t)(r + 8) * UU + col] =
                make_float2(c[mt][nt][2], c[mt][nt][3]);
        }
    }
}

// ---------------------------------------------------------------------------
// K5: logits[b][w][d] = sum_u v[u] * tanh(enc[b][d][u] + dec[b][w][u])
// Block: (b, 32-w tile, 64-d tile). Hardware tanh.approx (MUFU.TANH).
// Kept SEPARATE from softmax (fused variant measured +7 us).
// ---------------------------------------------------------------------------
__global__ __launch_bounds__(256) void k_logits(
    const float* __restrict__ v, float* __restrict__ out)
{
    const int b = blockIdx.x, wt = blockIdx.y, dt = blockIdx.z;

    __shared__ float enc_s[64][68];
    __shared__ float dec_s[32][68];
    __shared__ __align__(16) float v_s[64];

    const int tid = threadIdx.x;
    if (tid < 64) v_s[tid] = v[tid];

    #pragma unroll
    for (int i = 0; i < 4; i++) {
        int lin = i * 256 + tid;
        int d = lin >> 4, u4 = lin & 15;
        float4 val = *(const float4*)&g_enc[b][dt * 64 + d][u4 * 4];
        *(float4*)&enc_s[d][u4 * 4] = val;
    }
    #pragma unroll
    for (int i = 0; i < 2; i++) {
        int lin = i * 256 + tid;
        int w = lin >> 4, u4 = lin & 15;
        float4 val = *(const float4*)&g_dec[b][wt * 32 + w][u4 * 4];
        *(float4*)&dec_s[w][u4 * 4] = val;
    }
    __syncthreads();

    const int wloc = tid >> 3;     // 0..31
    const int dg   = tid & 7;      // 0..7
    float acc[8] = {0.f, 0.f, 0.f, 0.f, 0.f, 0.f, 0.f, 0.f};

    #pragma unroll
    for (int u4 = 0; u4 < 16; u4++) {
        float4 dv = *(const float4*)&dec_s[wloc][u4 * 4];
        float4 vv = *(const float4*)&v_s[u4 * 4];
        #pragma unroll
        for (int jj = 0; jj < 8; jj++) {
            float4 ev = *(const float4*)&enc_s[dg + 8 * jj][u4 * 4];
            acc[jj] = fmaf(vv.x, tanha(ev.x + dv.x), acc[jj]);
            acc[jj] = fmaf(vv.y, tanha(ev.y + dv.y), acc[jj]);
            acc[jj] = fmaf(vv.z, tanha(ev.z + dv.z), acc[jj]);
            acc[jj] = fmaf(vv.w, tanha(ev.w + dv.w), acc[jj]);
        }
    }

    const int w = wt * 32 + wloc;
    float* op = out + ((size_t)b * NEE + w) * NEE + dt * 64;
    #pragma unroll
    for (int jj = 0; jj < 8; jj++) op[dg + 8 * jj] = acc[jj];
}

// ---------------------------------------------------------------------------
// K6: in-place row softmax over last dim (256). One warp per row.
// ---------------------------------------------------------------------------
__global__ __launch_bounds__(256) void k_softmax(float* __restrict__ out)
{
    const int row  = blockIdx.x * 8 + (threadIdx.x >> 5);
    const int lane = threadIdx.x & 31;
    float* p = out + (size_t)row * NEE;

    float vals[8];
    float m = -1e30f;
    #pragma unroll
    for (int i = 0; i < 8; i++) {
        vals[i] = p[i * 32 + lane];
        m = fmaxf(m, vals[i]);
    }
    #pragma unroll
    for (int s = 16; s > 0; s >>= 1) m = fmaxf(m, __shfl_xor_sync(0xFFFFFFFFu, m, s));

    float sum = 0.0f;
    #pragma unroll
    for (int i = 0; i < 8; i++) {
        vals[i] = __expf(vals[i] - m);
        sum += vals[i];
    }
    #pragma unroll
    for (int s = 16; s > 0; s >>= 1) sum += __shfl_xor_sync(0xFFFFFFFFu, sum, s);

    const float inv = 1.0f / sum;
    #pragma unroll
    for (int i = 0; i < 8; i++) p[i * 32 + lane] = vals[i] * inv;
}

// ---------------------------------------------------------------------------
extern "C" void kernel_launch(void* const* d_in, const int* in_sizes, int n_in,
                              void* d_out, int out_size)
{
    const int*   sents  = (const int*)  d_in[0];
    const int*   datas  = (const int*)  d_in[1];
    const int*   slab   = (const int*)  d_in[2];
    const int*   dlab   = (const int*)  d_in[3];
    const float* emb    = (const float*)d_in[6];
    const float* Wi_f   = (const float*)d_in[7];
    const float* Wh_f   = (const float*)d_in[8];
    const float* b_f    = (const float*)d_in[9];
    const float* Wi_b   = (const float*)d_in[10];
    const float* Wh_b   = (const float*)d_in[11];
    const float* b_b    = (const float*)d_in[12];
    const float* WiD_f  = (const float*)d_in[13];
    const float* WhD_f  = (const float*)d_in[14];
    const float* bD_f   = (const float*)d_in[15];
    const float* WiD_b  = (const float*)d_in[16];
    const float* WhD_b  = (const float*)d_in[17];
    const float* bD_b   = (const float*)d_in[18];
    const float* W1     = (const float*)d_in[19];
    const float* W2     = (const float*)d_in[20];
    const float* v      = (const float*)d_in[21];
    float* out = (float*)d_out;

    k_xw<<<dim3(NROW / 128, 4, 4), 256>>>(
        sents, datas, emb,
        Wi_f, b_f, Wi_b, b_b, WiD_f, bD_f, WiD_b, bD_b);

    k_lstm<<<dim3(BB, 4), 256>>>(Wh_f, Wh_b, WhD_f, WhD_b);

    k_ent<<<dim3(BB, 2), 128>>>(slab, dlab);

    k_encdec<<<dim3(NROW / 128, 2), 256>>>(W1, W2);

    k_logits<<<dim3(BB, NEE / 32, NEE / 64), 256>>>(v, out);

    k_softmax<<<(BB * NEE) / 8, 256>>>(out);
}